// round 1
// baseline (speedup 1.0000x reference)
#include <cuda_runtime.h>
#include <cuda_bf16.h>
#include <math.h>

#define DIM 768
#define HEADS 12
#define HEAD_DIM 64
#define BATCH 64
#define SEQ 196
#define MTOT (BATCH * SEQ)      // 12544
#define SCALE 0.125f            // 64^-0.5

// ---------------- scratch (device globals; no allocation allowed) ----------------
__device__ float g_qk[(size_t)MTOT * 2 * DIM];   // (B*N, 1536)  q|k
__device__ float g_v[(size_t)MTOT * DIM];        // (B*N, 768)
__device__ float g_o[(size_t)MTOT * DIM];        // (B*N, 768)  attention out (B,N,H*hd)
__device__ float g_pos[HEADS * 729];             // [h][ (dy+13)*27 + (dx+13) ]

// ---------------- pos table: pos_map depends only on (dx,dy) in [-13,13]^2 ----------------
__global__ void pos_kernel(const float* __restrict__ w1,  // (768,2)
                           const float* __restrict__ b1,  // (768,)
                           const float* __restrict__ w2,  // (768,)
                           const float* __restrict__ b2,  // (12,)
                           float* __restrict__ out)       // (12,729)
{
    int c = blockIdx.x;                 // 0..728
    float dx = (float)(c % 27 - 13);
    float dy = (float)(c / 27 - 13);
    int h = threadIdx.x >> 5;           // 0..11 (block = 384 threads)
    int lane = threadIdx.x & 31;
    float sum = 0.f;
#pragma unroll
    for (int mm = lane; mm < HEAD_DIM; mm += 32) {
        int g = h * HEAD_DIM + mm;
        float t = fmaf(dx, w1[g * 2 + 0], fmaf(dy, w1[g * 2 + 1], b1[g]));
        t = fmaxf(t, 0.f);
        sum += t * w2[g];
    }
#pragma unroll
    for (int o = 16; o > 0; o >>= 1) sum += __shfl_xor_sync(0xffffffffu, sum, o);
    if (lane == 0) out[h * 729 + c] = sum + b2[h];
}

// ---------------- SGEMM: C[m][n] = sum_k A[m][k]*B[n][k] (+ bias[n]) ----------------
// A: (M,K) row-major, B: (N,K) row-major (weights stored (out,in)). All dims
// multiples of tile sizes for our shapes (M=12544, K=768, N in {1536,768}).
__global__ __launch_bounds__(256, 2)
void sgemm_tn(const float* __restrict__ A, const float* __restrict__ B,
              const float* __restrict__ bias, float* __restrict__ C,
              int M, int N, int K)
{
    const int BM = 128, BN = 128, BK = 16;
    __shared__ float As[BK][BM];
    __shared__ float Bs[BK][BN];

    int tid = threadIdx.x;              // 256
    int tr = tid >> 4;                  // 0..15
    int tc = tid & 15;                  // 0..15
    int m0 = blockIdx.y * BM;
    int n0 = blockIdx.x * BN;

    int lrow = tid >> 2;                // 0..63
    int lk4  = tid & 3;                 // 0..3

    float acc[8][8];
#pragma unroll
    for (int i = 0; i < 8; i++)
#pragma unroll
        for (int j = 0; j < 8; j++) acc[i][j] = 0.f;

    for (int k0 = 0; k0 < K; k0 += BK) {
#pragma unroll
        for (int l = 0; l < 2; l++) {
            int row = lrow + l * 64;
            float4 a = *(const float4*)&A[(size_t)(m0 + row) * K + k0 + lk4 * 4];
            As[lk4 * 4 + 0][row] = a.x;
            As[lk4 * 4 + 1][row] = a.y;
            As[lk4 * 4 + 2][row] = a.z;
            As[lk4 * 4 + 3][row] = a.w;
            float4 b = *(const float4*)&B[(size_t)(n0 + row) * K + k0 + lk4 * 4];
            Bs[lk4 * 4 + 0][row] = b.x;
            Bs[lk4 * 4 + 1][row] = b.y;
            Bs[lk4 * 4 + 2][row] = b.z;
            Bs[lk4 * 4 + 3][row] = b.w;
        }
        __syncthreads();
#pragma unroll
        for (int k = 0; k < BK; k++) {
            float ra[8], rb[8];
            *(float4*)&ra[0] = *(const float4*)&As[k][tr * 8];
            *(float4*)&ra[4] = *(const float4*)&As[k][tr * 8 + 4];
            *(float4*)&rb[0] = *(const float4*)&Bs[k][tc * 8];
            *(float4*)&rb[4] = *(const float4*)&Bs[k][tc * 8 + 4];
#pragma unroll
            for (int i = 0; i < 8; i++)
#pragma unroll
                for (int j = 0; j < 8; j++)
                    acc[i][j] = fmaf(ra[i], rb[j], acc[i][j]);
        }
        __syncthreads();
    }

    float bv[8];
    if (bias) {
        *(float4*)&bv[0] = *(const float4*)&bias[n0 + tc * 8];
        *(float4*)&bv[4] = *(const float4*)&bias[n0 + tc * 8 + 4];
    } else {
#pragma unroll
        for (int j = 0; j < 8; j++) bv[j] = 0.f;
    }
#pragma unroll
    for (int i = 0; i < 8; i++) {
        float4 o0, o1;
        o0.x = acc[i][0] + bv[0]; o0.y = acc[i][1] + bv[1];
        o0.z = acc[i][2] + bv[2]; o0.w = acc[i][3] + bv[3];
        o1.x = acc[i][4] + bv[4]; o1.y = acc[i][5] + bv[5];
        o1.z = acc[i][6] + bv[6]; o1.w = acc[i][7] + bv[7];
        size_t base = (size_t)(m0 + tr * 8 + i) * N + n0 + tc * 8;
        *(float4*)&C[base]     = o0;
        *(float4*)&C[base + 4] = o1;
    }
}

// ---------------- fused attention per (b,h) ----------------
// block = 256 threads (8 warps). smem: K (224 rows padded, stride 65),
// V (196 rows, stride 65), pos slice (729), p[8][196], qrow[8][64]
#define KROWS 224
#define KSTRIDE 65
#define ATTN_SMEM_FLOATS (KROWS * KSTRIDE + SEQ * KSTRIDE + 729 + 8 * SEQ + 8 * 64)

__global__ void attn_kernel(const float* __restrict__ qk,
                            const float* __restrict__ v,
                            const float* __restrict__ pos,
                            float* __restrict__ og)
{
    extern __shared__ float sm[];
    float* Ksh  = sm;                        // KROWS*65
    float* Vsh  = Ksh + KROWS * KSTRIDE;     // 196*65
    float* posh = Vsh + SEQ * KSTRIDE;       // 729
    float* pbuf = posh + 729;                // 8*196
    float* qr   = pbuf + 8 * SEQ;            // 8*64

    int bh = blockIdx.x;
    int b = bh / HEADS;
    int h = bh % HEADS;
    int tid = threadIdx.x;
    int w = tid >> 5;
    int lane = tid & 31;

    // stage K (pad rows 196..223 with zeros)
    for (int idx = tid; idx < KROWS * 16; idx += 256) {
        int j = idx >> 4, d4 = idx & 15;
        float4 val = make_float4(0.f, 0.f, 0.f, 0.f);
        if (j < SEQ)
            val = *(const float4*)&qk[(size_t)(b * SEQ + j) * (2 * DIM) + DIM + h * HEAD_DIM + d4 * 4];
        float* dst = &Ksh[j * KSTRIDE + d4 * 4];
        dst[0] = val.x; dst[1] = val.y; dst[2] = val.z; dst[3] = val.w;
    }
    // stage V
    for (int idx = tid; idx < SEQ * 16; idx += 256) {
        int j = idx >> 4, d4 = idx & 15;
        float4 val = *(const float4*)&v[(size_t)(b * SEQ + j) * DIM + h * HEAD_DIM + d4 * 4];
        float* dst = &Vsh[j * KSTRIDE + d4 * 4];
        dst[0] = val.x; dst[1] = val.y; dst[2] = val.z; dst[3] = val.w;
    }
    // stage pos slice for this head
    for (int c = tid; c < 729; c += 256) posh[c] = pos[h * 729 + c];
    __syncthreads();

    for (int r = w; r < SEQ; r += 8) {
        // q row -> smem
        const float* qrow_g = &qk[(size_t)(b * SEQ + r) * (2 * DIM) + h * HEAD_DIM];
        qr[w * 64 + lane]      = qrow_g[lane];
        qr[w * 64 + lane + 32] = qrow_g[lane + 32];
        __syncwarp();

        int rdiv = r / 14, rmod = r - rdiv * 14;

        // scores: 7-wide j register blocking
        float acc[7];
#pragma unroll
        for (int jj = 0; jj < 7; jj++) acc[jj] = 0.f;
#pragma unroll
        for (int d = 0; d < HEAD_DIM; d++) {
            float qd = qr[w * 64 + d];
#pragma unroll
            for (int jj = 0; jj < 7; jj++)
                acc[jj] = fmaf(qd, Ksh[(lane + jj * 32) * KSTRIDE + d], acc[jj]);
        }

        float sv[7];
        float mx = -1e30f;
#pragma unroll
        for (int jj = 0; jj < 7; jj++) {
            int j = lane + jj * 32;
            if (j < SEQ) {
                int jdiv = j / 14, jmod = j - jdiv * 14;
                float posv = posh[(jdiv - rdiv + 13) * 27 + (jmod - rmod + 13)];
                float s = acc[jj] * SCALE * posv;
                sv[jj] = s;
                mx = fmaxf(mx, s);
            } else {
                sv[jj] = -1e30f;
            }
        }
#pragma unroll
        for (int o = 16; o > 0; o >>= 1)
            mx = fmaxf(mx, __shfl_xor_sync(0xffffffffu, mx, o));

        float ssum = 0.f;
#pragma unroll
        for (int jj = 0; jj < 7; jj++) {
            int j = lane + jj * 32;
            if (j < SEQ) {
                float e = __expf(sv[jj] - mx);
                pbuf[w * SEQ + j] = e;
                ssum += e;
            }
        }
#pragma unroll
        for (int o = 16; o > 0; o >>= 1)
            ssum += __shfl_xor_sync(0xffffffffu, ssum, o);
        float inv = 1.f / ssum;
        __syncwarp();

        // out = p @ V
        float a0 = 0.f, a1 = 0.f;
#pragma unroll 4
        for (int j = 0; j < SEQ; j++) {
            float pj = pbuf[w * SEQ + j];
            a0 = fmaf(pj, Vsh[j * KSTRIDE + lane], a0);
            a1 = fmaf(pj, Vsh[j * KSTRIDE + lane + 32], a1);
        }
        float* orow = &og[(size_t)(b * SEQ + r) * DIM + h * HEAD_DIM];
        orow[lane]      = a0 * inv;
        orow[lane + 32] = a1 * inv;
        __syncwarp();
    }
}

// ---------------- launch ----------------
extern "C" void kernel_launch(void* const* d_in, const int* in_sizes, int n_in,
                              void* d_out, int out_size)
{
    const float* x      = (const float*)d_in[0];
    const float* qk_w   = (const float*)d_in[1];
    const float* v_w    = (const float*)d_in[2];
    const float* w1_w   = (const float*)d_in[3];
    const float* w1_b   = (const float*)d_in[4];
    const float* w2     = (const float*)d_in[5];
    const float* b2     = (const float*)d_in[6];
    const float* proj_w = (const float*)d_in[7];
    const float* proj_b = (const float*)d_in[8];
    float* out = (float*)d_out;

    float *qk_buf, *v_buf, *o_buf, *pos_buf;
    cudaGetSymbolAddress((void**)&qk_buf, g_qk);
    cudaGetSymbolAddress((void**)&v_buf, g_v);
    cudaGetSymbolAddress((void**)&o_buf, g_o);
    cudaGetSymbolAddress((void**)&pos_buf, g_pos);

    // 1) positional table (27x27 x 12 heads)
    pos_kernel<<<729, 384>>>(w1_w, w1_b, w2, b2, pos_buf);

    // 2) qk projection: (12544,768) x (1536,768)^T
    {
        dim3 grid(2 * DIM / 128, MTOT / 128);
        sgemm_tn<<<grid, 256>>>(x, qk_w, nullptr, qk_buf, MTOT, 2 * DIM, DIM);
    }
    // 3) v projection
    {
        dim3 grid(DIM / 128, MTOT / 128);
        sgemm_tn<<<grid, 256>>>(x, v_w, nullptr, v_buf, MTOT, DIM, DIM);
    }
    // 4) fused attention
    {
        int smem_bytes = ATTN_SMEM_FLOATS * sizeof(float);
        cudaFuncSetAttribute(attn_kernel, cudaFuncAttributeMaxDynamicSharedMemorySize, smem_bytes);
        attn_kernel<<<BATCH * HEADS, 256, smem_bytes>>>(qk_buf, v_buf, pos_buf, o_buf);
    }
    // 5) output projection with bias
    {
        dim3 grid(DIM / 128, MTOT / 128);
        sgemm_tn<<<grid, 256>>>(o_buf, proj_w, proj_b, out, MTOT, DIM, DIM);
    }
}

// round 2
// speedup vs baseline: 2.1710x; 2.1710x over previous
#include <cuda_runtime.h>
#include <cuda_bf16.h>
#include <math.h>
#include <stdint.h>

#define DIM 768
#define HEADS 12
#define HEAD_DIM 64
#define BATCH 64
#define SEQ 196
#define MTOT (BATCH * SEQ)      // 12544
#define SCALE 0.125f            // 64^-0.5

// ---------------- scratch (device globals; no allocation allowed) ----------------
__device__ float g_qk[(size_t)MTOT * 2 * DIM];   // (B*N, 1536)  q|k
__device__ float g_v[(size_t)MTOT * DIM];        // (B*N, 768)
__device__ float g_o[(size_t)MTOT * DIM];        // (B*N, 768)
__device__ float g_pos[HEADS * 729];             // [h][ (dy+13)*27 + (dx+13) ]

// ---------------- pos table ----------------
__global__ void pos_kernel(const float* __restrict__ w1,
                           const float* __restrict__ b1,
                           const float* __restrict__ w2,
                           const float* __restrict__ b2,
                           float* __restrict__ out)
{
    int c = blockIdx.x;                 // 0..728
    float dx = (float)(c % 27 - 13);
    float dy = (float)(c / 27 - 13);
    int h = threadIdx.x >> 5;
    int lane = threadIdx.x & 31;
    float sum = 0.f;
#pragma unroll
    for (int mm = lane; mm < HEAD_DIM; mm += 32) {
        int g = h * HEAD_DIM + mm;
        float t = fmaf(dx, w1[g * 2 + 0], fmaf(dy, w1[g * 2 + 1], b1[g]));
        t = fmaxf(t, 0.f);
        sum += t * w2[g];
    }
#pragma unroll
    for (int o = 16; o > 0; o >>= 1) sum += __shfl_xor_sync(0xffffffffu, sum, o);
    if (lane == 0) out[h * 729 + c] = sum + b2[h];
}

// ---------------- TF32 tensor-core GEMM ----------------
// C[m][n] = sum_k A[m][k] * B[n][k] (+ bias[n]).
// A: (M,K) row-major fp32. B: (N,K) row-major fp32 (weights (out,in)).
// BM=BN=128, BK=32. 8 warps, each computes 64x32 via m16n8k8 tf32 mma.

__device__ __forceinline__ uint32_t f2tf32(float x) {
    uint32_t r;
    asm("cvt.rna.tf32.f32 %0, %1;" : "=r"(r) : "f"(x));
    return r;
}

__device__ __forceinline__ void mma_tf32(float* c, const uint32_t* a, const uint32_t* b) {
    asm volatile(
        "mma.sync.aligned.m16n8k8.row.col.f32.tf32.tf32.f32 "
        "{%0,%1,%2,%3}, {%4,%5,%6,%7}, {%8,%9}, {%0,%1,%2,%3};\n"
        : "+f"(c[0]), "+f"(c[1]), "+f"(c[2]), "+f"(c[3])
        : "r"(a[0]), "r"(a[1]), "r"(a[2]), "r"(a[3]), "r"(b[0]), "r"(b[1]));
}

#define GBM 128
#define GBN 128
#define GBK 32
#define GSTR 36   // smem row stride in floats: frag loads AND float4 stores conflict-free

__global__ __launch_bounds__(256, 2)
void mma_tn(const float* __restrict__ A, const float* __restrict__ B,
            const float* __restrict__ bias, float* __restrict__ C,
            int M, int N, int K)
{
    __shared__ uint32_t As[GBM * GSTR];
    __shared__ uint32_t Bs[GBN * GSTR];

    int tid = threadIdx.x;
    int lane = tid & 31;
    int w = tid >> 5;
    int wm = w >> 2;            // 0..1   (m tile of 64)
    int wn = w & 3;             // 0..3   (n tile of 32)
    int m0 = blockIdx.y * GBM;
    int n0 = blockIdx.x * GBN;

    // loader coords: 4 passes, each pass: row=(tid>>3)+pass*32, f4=tid&7
    int lrow = tid >> 3;        // 0..31
    int lf4 = tid & 7;          // 0..7

    float acc[4][4][4];
#pragma unroll
    for (int i = 0; i < 4; i++)
#pragma unroll
        for (int j = 0; j < 4; j++)
#pragma unroll
            for (int t = 0; t < 4; t++) acc[i][j][t] = 0.f;

    for (int k0 = 0; k0 < K; k0 += GBK) {
#pragma unroll
        for (int p = 0; p < 4; p++) {
            int row = lrow + p * 32;
            float4 a = *(const float4*)&A[(size_t)(m0 + row) * K + k0 + lf4 * 4];
            uint32_t* d = &As[row * GSTR + lf4 * 4];
            d[0] = f2tf32(a.x); d[1] = f2tf32(a.y); d[2] = f2tf32(a.z); d[3] = f2tf32(a.w);
            float4 b = *(const float4*)&B[(size_t)(n0 + row) * K + k0 + lf4 * 4];
            uint32_t* e = &Bs[row * GSTR + lf4 * 4];
            e[0] = f2tf32(b.x); e[1] = f2tf32(b.y); e[2] = f2tf32(b.z); e[3] = f2tf32(b.w);
        }
        __syncthreads();

#pragma unroll
        for (int ks = 0; ks < 4; ks++) {
            int kb = ks * 8;
            uint32_t af[4][4], bf[4][2];
#pragma unroll
            for (int i = 0; i < 4; i++) {
                int r = wm * 64 + i * 16 + (lane >> 2);
                int c = kb + (lane & 3);
                af[i][0] = As[r * GSTR + c];
                af[i][1] = As[(r + 8) * GSTR + c];
                af[i][2] = As[r * GSTR + c + 4];
                af[i][3] = As[(r + 8) * GSTR + c + 4];
            }
#pragma unroll
            for (int j = 0; j < 4; j++) {
                int r = wn * 32 + j * 8 + (lane >> 2);
                int c = kb + (lane & 3);
                bf[j][0] = Bs[r * GSTR + c];
                bf[j][1] = Bs[r * GSTR + c + 4];
            }
#pragma unroll
            for (int i = 0; i < 4; i++)
#pragma unroll
                for (int j = 0; j < 4; j++)
                    mma_tf32(acc[i][j], af[i], bf[j]);
        }
        __syncthreads();
    }

    // epilogue: c0,c1 at (row, col..col+1), c2,c3 at (row+8, col..col+1)
#pragma unroll
    for (int i = 0; i < 4; i++) {
#pragma unroll
        for (int j = 0; j < 4; j++) {
            int row = m0 + wm * 64 + i * 16 + (lane >> 2);
            int col = n0 + wn * 32 + j * 8 + (lane & 3) * 2;
            float b0 = bias ? bias[col] : 0.f;
            float b1 = bias ? bias[col + 1] : 0.f;
            float2 v0 = make_float2(acc[i][j][0] + b0, acc[i][j][1] + b1);
            float2 v1 = make_float2(acc[i][j][2] + b0, acc[i][j][3] + b1);
            *(float2*)&C[(size_t)row * N + col] = v0;
            *(float2*)&C[(size_t)(row + 8) * N + col] = v1;
        }
    }
}

// ---------------- fused attention per (b,h), 4-row register tiling ----------------
#define KROWS 224
#define KSTRIDE 65
#define RT 4
#define ATTN_SMEM_FLOATS (KROWS * KSTRIDE + SEQ * KSTRIDE + 729 + 8 * RT * SEQ + 8 * RT * 64)

__global__ void attn_kernel(const float* __restrict__ qk,
                            const float* __restrict__ v,
                            const float* __restrict__ pos,
                            float* __restrict__ og)
{
    extern __shared__ float sm[];
    float* Ksh  = sm;                          // KROWS*65
    float* Vsh  = Ksh + KROWS * KSTRIDE;       // 196*65
    float* posh = Vsh + SEQ * KSTRIDE;         // 729
    float* pbuf = posh + 729;                  // 8*RT*196
    float* qr   = pbuf + 8 * RT * SEQ;         // 8*RT*64

    int bh = blockIdx.x;
    int b = bh / HEADS;
    int h = bh % HEADS;
    int tid = threadIdx.x;
    int w = tid >> 5;
    int lane = tid & 31;

    // stage K (rows 196..223 zero-padded)
    for (int idx = tid; idx < KROWS * 16; idx += 256) {
        int j = idx >> 4, d4 = idx & 15;
        float4 val = make_float4(0.f, 0.f, 0.f, 0.f);
        if (j < SEQ)
            val = *(const float4*)&qk[(size_t)(b * SEQ + j) * (2 * DIM) + DIM + h * HEAD_DIM + d4 * 4];
        float* dst = &Ksh[j * KSTRIDE + d4 * 4];
        dst[0] = val.x; dst[1] = val.y; dst[2] = val.z; dst[3] = val.w;
    }
    // stage V
    for (int idx = tid; idx < SEQ * 16; idx += 256) {
        int j = idx >> 4, d4 = idx & 15;
        float4 val = *(const float4*)&v[(size_t)(b * SEQ + j) * DIM + h * HEAD_DIM + d4 * 4];
        float* dst = &Vsh[j * KSTRIDE + d4 * 4];
        dst[0] = val.x; dst[1] = val.y; dst[2] = val.z; dst[3] = val.w;
    }
    for (int c = tid; c < 729; c += 256) posh[c] = pos[h * 729 + c];
    __syncthreads();

    float* myp = &pbuf[w * RT * SEQ];
    float* myq = &qr[w * RT * 64];

    for (int r0 = w * RT; r0 < SEQ; r0 += 8 * RT) {
        // stage 4 q rows into smem (cooperative within warp)
#pragma unroll
        for (int t = 0; t < 8; t++) {
            int idx = lane + t * 32;             // 0..255
            int rr = idx >> 6, d = idx & 63;
            myq[rr * 64 + d] = qk[(size_t)(b * SEQ + r0 + rr) * (2 * DIM) + h * HEAD_DIM + d];
        }
        __syncwarp();

        // scores: acc[rr][jj]
        float acc[RT][7];
#pragma unroll
        for (int rr = 0; rr < RT; rr++)
#pragma unroll
            for (int jj = 0; jj < 7; jj++) acc[rr][jj] = 0.f;

#pragma unroll 8
        for (int d = 0; d < HEAD_DIM; d++) {
            float kv[7];
#pragma unroll
            for (int jj = 0; jj < 7; jj++)
                kv[jj] = Ksh[(lane + jj * 32) * KSTRIDE + d];
            float qv[RT];
#pragma unroll
            for (int rr = 0; rr < RT; rr++) qv[rr] = myq[rr * 64 + d];
#pragma unroll
            for (int rr = 0; rr < RT; rr++)
#pragma unroll
                for (int jj = 0; jj < 7; jj++)
                    acc[rr][jj] = fmaf(qv[rr], kv[jj], acc[rr][jj]);
        }

        // softmax per row
        float inv[RT];
#pragma unroll
        for (int rr = 0; rr < RT; rr++) {
            int r = r0 + rr;
            int rdiv = r / 14, rmod = r - rdiv * 14;
            float sv[7];
            float mx = -1e30f;
#pragma unroll
            for (int jj = 0; jj < 7; jj++) {
                int j = lane + jj * 32;
                if (j < SEQ) {
                    int jdiv = j / 14, jmod = j - jdiv * 14;
                    float posv = posh[(jdiv - rdiv + 13) * 27 + (jmod - rmod + 13)];
                    float s = acc[rr][jj] * SCALE * posv;
                    sv[jj] = s;
                    mx = fmaxf(mx, s);
                } else {
                    sv[jj] = -1e30f;
                }
            }
#pragma unroll
            for (int o = 16; o > 0; o >>= 1)
                mx = fmaxf(mx, __shfl_xor_sync(0xffffffffu, mx, o));
            float ssum = 0.f;
#pragma unroll
            for (int jj = 0; jj < 7; jj++) {
                int j = lane + jj * 32;
                if (j < SEQ) {
                    float e = __expf(sv[jj] - mx);
                    myp[rr * SEQ + j] = e;
                    ssum += e;
                }
            }
#pragma unroll
            for (int o = 16; o > 0; o >>= 1)
                ssum += __shfl_xor_sync(0xffffffffu, ssum, o);
            inv[rr] = 1.f / ssum;
        }
        __syncwarp();

        // out = p @ V
        float o0[RT], o1[RT];
#pragma unroll
        for (int rr = 0; rr < RT; rr++) { o0[rr] = 0.f; o1[rr] = 0.f; }
#pragma unroll 2
        for (int j = 0; j < SEQ; j++) {
            float vj0 = Vsh[j * KSTRIDE + lane];
            float vj1 = Vsh[j * KSTRIDE + 32 + lane];
            float pv[RT];
#pragma unroll
            for (int rr = 0; rr < RT; rr++) pv[rr] = myp[rr * SEQ + j];
#pragma unroll
            for (int rr = 0; rr < RT; rr++) {
                o0[rr] = fmaf(pv[rr], vj0, o0[rr]);
                o1[rr] = fmaf(pv[rr], vj1, o1[rr]);
            }
        }
#pragma unroll
        for (int rr = 0; rr < RT; rr++) {
            float* orow = &og[(size_t)(b * SEQ + r0 + rr) * DIM + h * HEAD_DIM];
            orow[lane]      = o0[rr] * inv[rr];
            orow[lane + 32] = o1[rr] * inv[rr];
        }
        __syncwarp();
    }
}

// ---------------- launch ----------------
extern "C" void kernel_launch(void* const* d_in, const int* in_sizes, int n_in,
                              void* d_out, int out_size)
{
    const float* x      = (const float*)d_in[0];
    const float* qk_w   = (const float*)d_in[1];
    const float* v_w    = (const float*)d_in[2];
    const float* w1_w   = (const float*)d_in[3];
    const float* w1_b   = (const float*)d_in[4];
    const float* w2     = (const float*)d_in[5];
    const float* b2     = (const float*)d_in[6];
    const float* proj_w = (const float*)d_in[7];
    const float* proj_b = (const float*)d_in[8];
    float* out = (float*)d_out;

    float *qk_buf, *v_buf, *o_buf, *pos_buf;
    cudaGetSymbolAddress((void**)&qk_buf, g_qk);
    cudaGetSymbolAddress((void**)&v_buf, g_v);
    cudaGetSymbolAddress((void**)&o_buf, g_o);
    cudaGetSymbolAddress((void**)&pos_buf, g_pos);

    // 1) positional table
    pos_kernel<<<729, 384>>>(w1_w, w1_b, w2, b2, pos_buf);

    // 2) qk projection: (12544,1536) = x @ qk_w^T
    {
        dim3 grid(2 * DIM / GBN, MTOT / GBM);
        mma_tn<<<grid, 256>>>(x, qk_w, nullptr, qk_buf, MTOT, 2 * DIM, DIM);
    }
    // 3) v projection
    {
        dim3 grid(DIM / GBN, MTOT / GBM);
        mma_tn<<<grid, 256>>>(x, v_w, nullptr, v_buf, MTOT, DIM, DIM);
    }
    // 4) fused attention
    {
        int smem_bytes = ATTN_SMEM_FLOATS * sizeof(float);
        cudaFuncSetAttribute(attn_kernel, cudaFuncAttributeMaxDynamicSharedMemorySize, smem_bytes);
        attn_kernel<<<BATCH * HEADS, 256, smem_bytes>>>(qk_buf, v_buf, pos_buf, o_buf);
    }
    // 5) output projection with bias
    {
        dim3 grid(DIM / GBN, MTOT / GBM);
        mma_tn<<<grid, 256>>>(o_buf, proj_w, proj_b, out, MTOT, DIM, DIM);
    }
}

// round 5
// speedup vs baseline: 2.3576x; 1.0859x over previous
#include <cuda_runtime.h>
#include <cuda_bf16.h>
#include <math.h>
#include <stdint.h>

#define DIM 768
#define HEADS 12
#define HEAD_DIM 64
#define BATCH 64
#define SEQ 196
#define MTOT (BATCH * SEQ)      // 12544
#define SCALE 0.125f

// ---------------- scratch ----------------
__device__ float g_qk[(size_t)MTOT * 2 * DIM];
__device__ float g_v[(size_t)MTOT * DIM];
__device__ float g_o[(size_t)MTOT * DIM];
__device__ float g_pos[HEADS * 729];

// ---------------- pos table ----------------
__global__ void pos_kernel(const float* __restrict__ w1,
                           const float* __restrict__ b1,
                           const float* __restrict__ w2,
                           const float* __restrict__ b2,
                           float* __restrict__ out)
{
    int c = blockIdx.x;
    float dx = (float)(c % 27 - 13);
    float dy = (float)(c / 27 - 13);
    int h = threadIdx.x >> 5;
    int lane = threadIdx.x & 31;
    float sum = 0.f;
#pragma unroll
    for (int mm = lane; mm < HEAD_DIM; mm += 32) {
        int g = h * HEAD_DIM + mm;
        float t = fmaf(dx, w1[g * 2 + 0], fmaf(dy, w1[g * 2 + 1], b1[g]));
        t = fmaxf(t, 0.f);
        sum += t * w2[g];
    }
#pragma unroll
    for (int o = 16; o > 0; o >>= 1) sum += __shfl_xor_sync(0xffffffffu, sum, o);
    if (lane == 0) out[h * 729 + c] = sum + b2[h];
}

// ---------------- common tf32 helpers ----------------
__device__ __forceinline__ uint32_t f2tf32(float x) {
    uint32_t r;
    asm("cvt.rna.tf32.f32 %0, %1;" : "=r"(r) : "f"(x));
    return r;
}

__device__ __forceinline__ void mma_tf32(float* c, const uint32_t* a, uint32_t b0, uint32_t b1) {
    asm volatile(
        "mma.sync.aligned.m16n8k8.row.col.f32.tf32.tf32.f32 "
        "{%0,%1,%2,%3}, {%4,%5,%6,%7}, {%8,%9}, {%0,%1,%2,%3};\n"
        : "+f"(c[0]), "+f"(c[1]), "+f"(c[2]), "+f"(c[3])
        : "r"(a[0]), "r"(a[1]), "r"(a[2]), "r"(a[3]), "r"(b0), "r"(b1));
}

// ---------------- TF32 tensor-core GEMM (unchanged from R2) ----------------
#define GBM 128
#define GBN 128
#define GBK 32
#define GSTR 36

__global__ __launch_bounds__(256, 2)
void mma_tn(const float* __restrict__ A, const float* __restrict__ B,
            const float* __restrict__ bias, float* __restrict__ C,
            int M, int N, int K)
{
    __shared__ uint32_t As[GBM * GSTR];
    __shared__ uint32_t Bs[GBN * GSTR];

    int tid = threadIdx.x;
    int lane = tid & 31;
    int w = tid >> 5;
    int wm = w >> 2;
    int wn = w & 3;
    int m0 = blockIdx.y * GBM;
    int n0 = blockIdx.x * GBN;

    int lrow = tid >> 3;
    int lf4 = tid & 7;

    float acc[4][4][4];
#pragma unroll
    for (int i = 0; i < 4; i++)
#pragma unroll
        for (int j = 0; j < 4; j++)
#pragma unroll
            for (int t = 0; t < 4; t++) acc[i][j][t] = 0.f;

    for (int k0 = 0; k0 < K; k0 += GBK) {
#pragma unroll
        for (int p = 0; p < 4; p++) {
            int row = lrow + p * 32;
            float4 a = *(const float4*)&A[(size_t)(m0 + row) * K + k0 + lf4 * 4];
            uint32_t* d = &As[row * GSTR + lf4 * 4];
            d[0] = f2tf32(a.x); d[1] = f2tf32(a.y); d[2] = f2tf32(a.z); d[3] = f2tf32(a.w);
            float4 b = *(const float4*)&B[(size_t)(n0 + row) * K + k0 + lf4 * 4];
            uint32_t* e = &Bs[row * GSTR + lf4 * 4];
            e[0] = f2tf32(b.x); e[1] = f2tf32(b.y); e[2] = f2tf32(b.z); e[3] = f2tf32(b.w);
        }
        __syncthreads();

#pragma unroll
        for (int ks = 0; ks < 4; ks++) {
            int kb = ks * 8;
            uint32_t af[4][4], bf[4][2];
#pragma unroll
            for (int i = 0; i < 4; i++) {
                int r = wm * 64 + i * 16 + (lane >> 2);
                int c = kb + (lane & 3);
                af[i][0] = As[r * GSTR + c];
                af[i][1] = As[(r + 8) * GSTR + c];
                af[i][2] = As[r * GSTR + c + 4];
                af[i][3] = As[(r + 8) * GSTR + c + 4];
            }
#pragma unroll
            for (int j = 0; j < 4; j++) {
                int r = wn * 32 + j * 8 + (lane >> 2);
                int c = kb + (lane & 3);
                bf[j][0] = Bs[r * GSTR + c];
                bf[j][1] = Bs[r * GSTR + c + 4];
            }
#pragma unroll
            for (int i = 0; i < 4; i++)
#pragma unroll
                for (int j = 0; j < 4; j++)
                    mma_tf32(acc[i][j], af[i], bf[j][0], bf[j][1]);
        }
        __syncthreads();
    }

#pragma unroll
    for (int i = 0; i < 4; i++) {
#pragma unroll
        for (int j = 0; j < 4; j++) {
            int row = m0 + wm * 64 + i * 16 + (lane >> 2);
            int col = n0 + wn * 32 + j * 8 + (lane & 3) * 2;
            float b0 = bias ? bias[col] : 0.f;
            float b1 = bias ? bias[col + 1] : 0.f;
            float2 v0 = make_float2(acc[i][j][0] + b0, acc[i][j][1] + b1);
            float2 v1 = make_float2(acc[i][j][2] + b0, acc[i][j][3] + b1);
            *(float2*)&C[(size_t)row * N + col] = v0;
            *(float2*)&C[(size_t)(row + 8) * N + col] = v1;
        }
    }
}

// ---------------- MMA attention: one block per (b,h) ----------------
// smem (tf32 stored as uint32): K [200][68], Vt [64][204], pos[729],
// per-warp P buffer [16][204]. S = Q@K^T via m16n8k8, softmax in regs,
// O = P@V via m16n8k8.
#define KSTR 68
#define PSTR 204
#define NPAD 200
#define ATTN_SM_WORDS (NPAD * KSTR + 64 * PSTR + 729 + 8 * 16 * PSTR)

__global__ __launch_bounds__(256, 1)
void attn_mma(const float* __restrict__ qk,
              const float* __restrict__ v,
              const float* __restrict__ pos,
              float* __restrict__ og)
{
    extern __shared__ uint32_t smu[];
    uint32_t* Ksh  = smu;                        // [200][68]
    uint32_t* Vts  = Ksh + NPAD * KSTR;          // [64][204]
    float*    posh = (float*)(Vts + 64 * PSTR);  // 729
    uint32_t* Pb   = (uint32_t*)(posh + 729);    // 8 x [16][204]

    int bh = blockIdx.x;
    int b = bh / HEADS;
    int h = bh % HEADS;
    int tid = threadIdx.x;
    int w = tid >> 5;
    int lane = tid & 31;
    int lq = lane >> 2;       // 0..7
    int lr = lane & 3;        // 0..3

    // ---- stage K (rows 196..199 zero), convert to tf32 ----
    for (int idx = tid; idx < NPAD * 16; idx += 256) {
        int j = idx >> 4, d4 = idx & 15;
        float4 val = make_float4(0.f, 0.f, 0.f, 0.f);
        if (j < SEQ)
            val = *(const float4*)&qk[(size_t)(b * SEQ + j) * (2 * DIM) + DIM + h * HEAD_DIM + d4 * 4];
        uint32_t* dst = &Ksh[j * KSTR + d4 * 4];
        dst[0] = f2tf32(val.x); dst[1] = f2tf32(val.y);
        dst[2] = f2tf32(val.z); dst[3] = f2tf32(val.w);
    }
    // ---- stage V transposed: Vt[d][j] (cols 196..199 zero) ----
    for (int idx = tid; idx < NPAD * 16; idx += 256) {
        int j = idx >> 4, d4 = idx & 15;
        float4 val = make_float4(0.f, 0.f, 0.f, 0.f);
        if (j < SEQ)
            val = *(const float4*)&v[(size_t)(b * SEQ + j) * DIM + h * HEAD_DIM + d4 * 4];
        Vts[(d4 * 4 + 0) * PSTR + j] = f2tf32(val.x);
        Vts[(d4 * 4 + 1) * PSTR + j] = f2tf32(val.y);
        Vts[(d4 * 4 + 2) * PSTR + j] = f2tf32(val.z);
        Vts[(d4 * 4 + 3) * PSTR + j] = f2tf32(val.w);
    }
    for (int c = tid; c < 729; c += 256) posh[c] = pos[h * 729 + c];
    __syncthreads();

    uint32_t* Pw = Pb + w * 16 * PSTR;

    for (int mt = w; mt < 13; mt += 8) {
        int m0 = mt * 16;

        // ---- stage this warp's 16x64 Q tile into Pw (stride KSTR), tf32 ----
#pragma unroll
        for (int it = 0; it < 8; it++) {
            int idx = lane + it * 32;           // 0..255
            int rr = idx >> 4, d4 = idx & 15;
            int r = m0 + rr; if (r > 195) r = 195;
            float4 qv = *(const float4*)&qk[(size_t)(b * SEQ + r) * (2 * DIM) + h * HEAD_DIM + d4 * 4];
            uint32_t* dst = &Pw[rr * KSTR + d4 * 4];
            dst[0] = f2tf32(qv.x); dst[1] = f2tf32(qv.y);
            dst[2] = f2tf32(qv.z); dst[3] = f2tf32(qv.w);
        }
        __syncwarp();

        // ---- A fragments for all 8 k-steps ----
        uint32_t af[8][4];
#pragma unroll
        for (int ks = 0; ks < 8; ks++) {
            int c = lr + ks * 8;
            af[ks][0] = Pw[lq * KSTR + c];
            af[ks][1] = Pw[(lq + 8) * KSTR + c];
            af[ks][2] = Pw[lq * KSTR + c + 4];
            af[ks][3] = Pw[(lq + 8) * KSTR + c + 4];
        }

        // ---- scores: S(16 x 200) ----
        float acc[25][4];
#pragma unroll
        for (int nt = 0; nt < 25; nt++)
#pragma unroll
            for (int t = 0; t < 4; t++) acc[nt][t] = 0.f;

#pragma unroll
        for (int ks = 0; ks < 8; ks++) {
#pragma unroll
            for (int nt = 0; nt < 25; nt++) {
                int nr = nt * 8 + lq;
                uint32_t b0 = Ksh[nr * KSTR + ks * 8 + lr];
                uint32_t b1 = Ksh[nr * KSTR + ks * 8 + lr + 4];
                mma_tf32(acc[nt], af[ks], b0, b1);
            }
        }

        // ---- scale * pos, masking, row max ----
        int r1 = m0 + lq, r2 = r1 + 8;
        int r1c = r1 > 195 ? 195 : r1;
        int r2c = r2 > 195 ? 195 : r2;
        int r1d = r1c / 14, r1m = r1c - r1d * 14;
        int r2d = r2c / 14, r2m = r2c - r2d * 14;
        float mx1 = -1e30f, mx2 = -1e30f;
#pragma unroll
        for (int nt = 0; nt < 25; nt++) {
#pragma unroll
            for (int t = 0; t < 2; t++) {
                int c = nt * 8 + lr * 2 + t;
                int cc = c > 195 ? 195 : c;
                int cd = cc / 14, cm = cc - cd * 14;
                float p1 = posh[(cd - r1d + 13) * 27 + (cm - r1m + 13)];
                float p2 = posh[(cd - r2d + 13) * 27 + (cm - r2m + 13)];
                float s1 = acc[nt][t] * SCALE * p1;
                float s2 = acc[nt][2 + t] * SCALE * p2;
                if (c > 195) { s1 = -1e30f; s2 = -1e30f; }
                acc[nt][t] = s1;
                acc[nt][2 + t] = s2;
                mx1 = fmaxf(mx1, s1);
                mx2 = fmaxf(mx2, s2);
            }
        }
        mx1 = fmaxf(mx1, __shfl_xor_sync(0xffffffffu, mx1, 1));
        mx1 = fmaxf(mx1, __shfl_xor_sync(0xffffffffu, mx1, 2));
        mx2 = fmaxf(mx2, __shfl_xor_sync(0xffffffffu, mx2, 1));
        mx2 = fmaxf(mx2, __shfl_xor_sync(0xffffffffu, mx2, 2));

        float sum1 = 0.f, sum2 = 0.f;
#pragma unroll
        for (int nt = 0; nt < 25; nt++) {
#pragma unroll
            for (int t = 0; t < 2; t++) {
                float e1 = __expf(acc[nt][t] - mx1);
                float e2 = __expf(acc[nt][2 + t] - mx2);
                acc[nt][t] = e1;
                acc[nt][2 + t] = e2;
                sum1 += e1;
                sum2 += e2;
            }
        }
        sum1 += __shfl_xor_sync(0xffffffffu, sum1, 1);
        sum1 += __shfl_xor_sync(0xffffffffu, sum1, 2);
        sum2 += __shfl_xor_sync(0xffffffffu, sum2, 1);
        sum2 += __shfl_xor_sync(0xffffffffu, sum2, 2);
        float inv1 = 1.f / sum1;
        float inv2 = 1.f / sum2;

        // ---- store normalized P (tf32) into Pw, stride PSTR ----
        __syncwarp();
#pragma unroll
        for (int nt = 0; nt < 25; nt++) {
            int c0 = nt * 8 + lr * 2;
            Pw[lq * PSTR + c0]           = f2tf32(acc[nt][0] * inv1);
            Pw[lq * PSTR + c0 + 1]       = f2tf32(acc[nt][1] * inv1);
            Pw[(lq + 8) * PSTR + c0]     = f2tf32(acc[nt][2] * inv2);
            Pw[(lq + 8) * PSTR + c0 + 1] = f2tf32(acc[nt][3] * inv2);
        }
        __syncwarp();

        // ---- O(16 x 64) = P @ V ----
        float ao[8][4];
#pragma unroll
        for (int nt = 0; nt < 8; nt++)
#pragma unroll
            for (int t = 0; t < 4; t++) ao[nt][t] = 0.f;

#pragma unroll
        for (int ks = 0; ks < 25; ks++) {
            uint32_t pa[4];
            int c = ks * 8 + lr;
            pa[0] = Pw[lq * PSTR + c];
            pa[1] = Pw[(lq + 8) * PSTR + c];
            pa[2] = Pw[lq * PSTR + c + 4];
            pa[3] = Pw[(lq + 8) * PSTR + c + 4];
#pragma unroll
            for (int nt = 0; nt < 8; nt++) {
                int nr = nt * 8 + lq;
                uint32_t b0 = Vts[nr * PSTR + ks * 8 + lr];
                uint32_t b1 = Vts[nr * PSTR + ks * 8 + lr + 4];
                mma_tf32(ao[nt], pa, b0, b1);
            }
        }

        // ---- write O ----
#pragma unroll
        for (int nt = 0; nt < 8; nt++) {
            int c = nt * 8 + lr * 2;
            if (r1 < SEQ)
                *(float2*)&og[(size_t)(b * SEQ + r1) * DIM + h * HEAD_DIM + c] =
                    make_float2(ao[nt][0], ao[nt][1]);
            if (r2 < SEQ)
                *(float2*)&og[(size_t)(b * SEQ + r2) * DIM + h * HEAD_DIM + c] =
                    make_float2(ao[nt][2], ao[nt][3]);
        }
        __syncwarp();
    }
}

// ---------------- launch ----------------
extern "C" void kernel_launch(void* const* d_in, const int* in_sizes, int n_in,
                              void* d_out, int out_size)
{
    const float* x      = (const float*)d_in[0];
    const float* qk_w   = (const float*)d_in[1];
    const float* v_w    = (const float*)d_in[2];
    const float* w1_w   = (const float*)d_in[3];
    const float* w1_b   = (const float*)d_in[4];
    const float* w2     = (const float*)d_in[5];
    const float* b2     = (const float*)d_in[6];
    const float* proj_w = (const float*)d_in[7];
    const float* proj_b = (const float*)d_in[8];
    float* out = (float*)d_out;

    float *qk_buf, *v_buf, *o_buf, *pos_buf;
    cudaGetSymbolAddress((void**)&qk_buf, g_qk);
    cudaGetSymbolAddress((void**)&v_buf, g_v);
    cudaGetSymbolAddress((void**)&o_buf, g_o);
    cudaGetSymbolAddress((void**)&pos_buf, g_pos);

    pos_kernel<<<729, 384>>>(w1_w, w1_b, w2, b2, pos_buf);

    {
        dim3 grid(2 * DIM / GBN, MTOT / GBM);
        mma_tn<<<grid, 256>>>(x, qk_w, nullptr, qk_buf, MTOT, 2 * DIM, DIM);
    }
    {
        dim3 grid(DIM / GBN, MTOT / GBM);
        mma_tn<<<grid, 256>>>(x, v_w, nullptr, v_buf, MTOT, DIM, DIM);
    }
    {
        int smem_bytes = ATTN_SM_WORDS * 4;
        cudaFuncSetAttribute(attn_mma, cudaFuncAttributeMaxDynamicSharedMemorySize, smem_bytes);
        attn_mma<<<BATCH * HEADS, 256, smem_bytes>>>(qk_buf, v_buf, pos_buf, o_buf);
    }
    {
        dim3 grid(DIM / GBN, MTOT / GBM);
        mma_tn<<<grid, 256>>>(o_buf, proj_w, proj_b, out, MTOT, DIM, DIM);
    }
}

// round 7
// speedup vs baseline: 4.8830x; 2.0712x over previous
#include <cuda_runtime.h>
#include <cuda_fp16.h>
#include <math.h>
#include <stdint.h>

#define DIM 768
#define HEADS 12
#define HEAD_DIM 64
#define BATCH 64
#define SEQ 196
#define MTOT (BATCH * SEQ)      // 12544
#define SCALE 0.125f

// ---------------- scratch ----------------
__device__ float g_qk[(size_t)MTOT * 2 * DIM];
__device__ float g_v[(size_t)MTOT * DIM];
__device__ float g_o[(size_t)MTOT * DIM];
__device__ float g_pos[HEADS * 729];

// ---------------- helpers ----------------
__device__ __forceinline__ uint32_t packh2(float x, float y) {
    __half2 h = __floats2half2_rn(x, y);
    return *(uint32_t*)&h;
}

__device__ __forceinline__ void mma_f16(float* c, const uint32_t* a, uint32_t b0, uint32_t b1) {
    asm volatile(
        "mma.sync.aligned.m16n8k16.row.col.f32.f16.f16.f32 "
        "{%0,%1,%2,%3}, {%4,%5,%6,%7}, {%8,%9}, {%0,%1,%2,%3};\n"
        : "+f"(c[0]), "+f"(c[1]), "+f"(c[2]), "+f"(c[3])
        : "r"(a[0]), "r"(a[1]), "r"(a[2]), "r"(a[3]), "r"(b0), "r"(b1));
}

// ---------------- pos table ----------------
__global__ void pos_kernel(const float* __restrict__ w1,
                           const float* __restrict__ b1,
                           const float* __restrict__ w2,
                           const float* __restrict__ b2,
                           float* __restrict__ out)
{
    int c = blockIdx.x;
    float dx = (float)(c % 27 - 13);
    float dy = (float)(c / 27 - 13);
    int h = threadIdx.x >> 5;
    int lane = threadIdx.x & 31;
    float sum = 0.f;
#pragma unroll
    for (int mm = lane; mm < HEAD_DIM; mm += 32) {
        int g = h * HEAD_DIM + mm;
        float t = fmaf(dx, w1[g * 2 + 0], fmaf(dy, w1[g * 2 + 1], b1[g]));
        t = fmaxf(t, 0.f);
        sum += t * w2[g];
    }
#pragma unroll
    for (int o = 16; o > 0; o >>= 1) sum += __shfl_xor_sync(0xffffffffu, sum, o);
    if (lane == 0) out[h * 729 + c] = sum + b2[h];
}

// ---------------- FP16 tensor-core GEMM ----------------
// C[m][n] = sum_k A[m][k]*B[n][k] (+ bias[n]).
// BM=BN=128, BK=32. 8 warps, each 64x32 via m16n8k16. smem stride 40 halves (20 words).
#define GSTRW 20   // words per smem row (32 halves data + 8 pad)

__global__ __launch_bounds__(256, 2)
void gemm_f16(const float* __restrict__ A, const float* __restrict__ B,
              const float* __restrict__ bias, float* __restrict__ C,
              int M, int N, int K)
{
    __shared__ uint32_t As[128 * GSTRW];
    __shared__ uint32_t Bs[128 * GSTRW];

    int tid = threadIdx.x;
    int lane = tid & 31;
    int w = tid >> 5;
    int wm = w >> 2;            // 0..1
    int wn = w & 3;             // 0..3
    int lq = lane >> 2;         // 0..7
    int lr = lane & 3;          // 0..3
    int m0 = blockIdx.y * 128;
    int n0 = blockIdx.x * 128;

    int lrow = tid >> 3;        // 0..31
    int lf4 = tid & 7;          // 0..7

    float acc[4][4][4];
#pragma unroll
    for (int i = 0; i < 4; i++)
#pragma unroll
        for (int j = 0; j < 4; j++)
#pragma unroll
            for (int t = 0; t < 4; t++) acc[i][j][t] = 0.f;

    for (int k0 = 0; k0 < K; k0 += 32) {
#pragma unroll
        for (int p = 0; p < 4; p++) {
            int row = lrow + p * 32;
            float4 a = *(const float4*)&A[(size_t)(m0 + row) * K + k0 + lf4 * 4];
            uint2 ap;
            ap.x = packh2(a.x, a.y);
            ap.y = packh2(a.z, a.w);
            *(uint2*)&As[row * GSTRW + lf4 * 2] = ap;
            float4 b = *(const float4*)&B[(size_t)(n0 + row) * K + k0 + lf4 * 4];
            uint2 bp;
            bp.x = packh2(b.x, b.y);
            bp.y = packh2(b.z, b.w);
            *(uint2*)&Bs[row * GSTRW + lf4 * 2] = bp;
        }
        __syncthreads();

#pragma unroll
        for (int ks = 0; ks < 2; ks++) {
            int kb2 = ks * 8;               // word offset of this k16 step
            uint32_t af[4][4], bf[4][2];
#pragma unroll
            for (int i = 0; i < 4; i++) {
                int r = wm * 64 + i * 16 + lq;
                af[i][0] = As[r * GSTRW + kb2 + lr];
                af[i][1] = As[(r + 8) * GSTRW + kb2 + lr];
                af[i][2] = As[r * GSTRW + kb2 + 4 + lr];
                af[i][3] = As[(r + 8) * GSTRW + kb2 + 4 + lr];
            }
#pragma unroll
            for (int j = 0; j < 4; j++) {
                int n = wn * 32 + j * 8 + lq;
                bf[j][0] = Bs[n * GSTRW + kb2 + lr];
                bf[j][1] = Bs[n * GSTRW + kb2 + 4 + lr];
            }
#pragma unroll
            for (int i = 0; i < 4; i++)
#pragma unroll
                for (int j = 0; j < 4; j++)
                    mma_f16(acc[i][j], af[i], bf[j][0], bf[j][1]);
        }
        __syncthreads();
    }

#pragma unroll
    for (int i = 0; i < 4; i++) {
#pragma unroll
        for (int j = 0; j < 4; j++) {
            int row = m0 + wm * 64 + i * 16 + lq;
            int col = n0 + wn * 32 + j * 8 + lr * 2;
            float b0 = bias ? bias[col] : 0.f;
            float b1 = bias ? bias[col + 1] : 0.f;
            *(float2*)&C[(size_t)row * N + col] =
                make_float2(acc[i][j][0] + b0, acc[i][j][1] + b1);
            *(float2*)&C[(size_t)(row + 8) * N + col] =
                make_float2(acc[i][j][2] + b0, acc[i][j][3] + b1);
        }
    }
}

// ---------------- FP16 MMA attention: one block per (b,h) ----------------
// smem (halves): K [208][72], Vt [64][216], pos[729] f32, colcode[208] int.
// S(16x208) per warp via m16n8k16; P fragments repacked from S accumulator
// in-thread (C-frag layout == A-frag k-layout); O = P@V via m16n8k16.
#define KSH_W 36            // words per K row (72 halves)
#define VTS_W 108           // words per Vt row (216 halves)
#define NPAD 208
#define NT 26
#define ATTN_SM_WORDS (NPAD * KSH_W + 64 * VTS_W + 729 + NPAD)

__global__ __launch_bounds__(256, 1)
void attn_mma(const float* __restrict__ qk,
              const float* __restrict__ v,
              const float* __restrict__ pos,
              float* __restrict__ og)
{
    extern __shared__ uint32_t smu[];
    uint32_t* Kw   = smu;                        // [208][36] words
    uint32_t* Vw   = Kw + NPAD * KSH_W;          // [64][108] words
    float*    posh = (float*)(Vw + 64 * VTS_W);  // 729
    int*      colc = (int*)(posh + 729);         // 208

    int bh = blockIdx.x;
    int b = bh / HEADS;
    int h = bh % HEADS;
    int tid = threadIdx.x;
    int w = tid >> 5;
    int lane = tid & 31;
    int lq = lane >> 2;       // 0..7
    int lr = lane & 3;        // 0..3

    // ---- zero pad regions: K rows 196..207, Vt cols (words 98..107) ----
    for (int idx = tid; idx < 12 * KSH_W; idx += 256)
        Kw[196 * KSH_W + idx] = 0;
    for (int idx = tid; idx < 64 * 10; idx += 256) {
        int d = idx / 10, wz = 98 + idx % 10;
        Vw[d * VTS_W + wz] = 0;
    }

    // ---- stage K rows 0..195 as half2 pairs ----
    for (int idx = tid; idx < SEQ * 16; idx += 256) {
        int j = idx >> 4, d4 = idx & 15;
        float4 val = *(const float4*)&qk[(size_t)(b * SEQ + j) * (2 * DIM) + DIM + h * HEAD_DIM + d4 * 4];
        uint2 p;
        p.x = packh2(val.x, val.y);
        p.y = packh2(val.z, val.w);
        *(uint2*)&Kw[j * KSH_W + d4 * 2] = p;
    }
    // ---- stage V transposed: Vt[d][j] halves ----
    {
        __half* Vh = (__half*)Vw;
        for (int idx = tid; idx < SEQ * 16; idx += 256) {
            int j = idx >> 4, d4 = idx & 15;
            float4 val = *(const float4*)&v[(size_t)(b * SEQ + j) * DIM + h * HEAD_DIM + d4 * 4];
            Vh[(d4 * 4 + 0) * (VTS_W * 2) + j] = __float2half(val.x);
            Vh[(d4 * 4 + 1) * (VTS_W * 2) + j] = __float2half(val.y);
            Vh[(d4 * 4 + 2) * (VTS_W * 2) + j] = __float2half(val.z);
            Vh[(d4 * 4 + 3) * (VTS_W * 2) + j] = __float2half(val.w);
        }
    }
    for (int c = tid; c < 729; c += 256) posh[c] = pos[h * 729 + c];
    for (int c = tid; c < NPAD; c += 256) {
        int cc = c > 195 ? 195 : c;
        colc[c] = (cc / 14) * 27 + (cc % 14);
    }
    __syncthreads();

    for (int mt = w; mt < 13; mt += 8) {
        int m0 = mt * 16;
        int r1 = m0 + lq, r2 = r1 + 8;
        int r1c = r1 > 195 ? 195 : r1;
        int r2c = r2 > 195 ? 195 : r2;
        const float* q1 = &qk[(size_t)(b * SEQ + r1c) * (2 * DIM) + h * HEAD_DIM];
        const float* q2 = &qk[(size_t)(b * SEQ + r2c) * (2 * DIM) + h * HEAD_DIM];

        // ---- Q fragments direct from global (float2 -> half2) ----
        uint32_t af[4][4];
#pragma unroll
        for (int ks = 0; ks < 4; ks++) {
            float2 t;
            t = *(const float2*)&q1[16 * ks + 2 * lr];
            af[ks][0] = packh2(t.x, t.y);
            t = *(const float2*)&q2[16 * ks + 2 * lr];
            af[ks][1] = packh2(t.x, t.y);
            t = *(const float2*)&q1[16 * ks + 8 + 2 * lr];
            af[ks][2] = packh2(t.x, t.y);
            t = *(const float2*)&q2[16 * ks + 8 + 2 * lr];
            af[ks][3] = packh2(t.x, t.y);
        }

        // ---- scores S(16 x 208) ----
        float acc[NT][4];
#pragma unroll
        for (int nt = 0; nt < NT; nt++)
#pragma unroll
            for (int t = 0; t < 4; t++) acc[nt][t] = 0.f;

#pragma unroll
        for (int ks = 0; ks < 4; ks++) {
#pragma unroll
            for (int nt = 0; nt < NT; nt++) {
                int nr = nt * 8 + lq;
                uint32_t b0 = Kw[nr * KSH_W + 8 * ks + lr];
                uint32_t b1 = Kw[nr * KSH_W + 8 * ks + 4 + lr];
                mma_f16(acc[nt], af[ks], b0, b1);
            }
        }

        // ---- scale * pos, masking, row max / exp / sum ----
        int base1 = (13 - r1c / 14) * 27 + (13 - r1c % 14);
        int base2 = (13 - r2c / 14) * 27 + (13 - r2c % 14);
        float mx1 = -1e30f, mx2 = -1e30f;
#pragma unroll
        for (int nt = 0; nt < NT; nt++) {
#pragma unroll
            for (int t = 0; t < 2; t++) {
                int c = nt * 8 + lr * 2 + t;
                int code = colc[c];
                float p1 = posh[code + base1];
                float p2 = posh[code + base2];
                float s1 = acc[nt][t] * SCALE * p1;
                float s2 = acc[nt][2 + t] * SCALE * p2;
                if (c > 195) { s1 = -1e30f; s2 = -1e30f; }
                acc[nt][t] = s1;
                acc[nt][2 + t] = s2;
                mx1 = fmaxf(mx1, s1);
                mx2 = fmaxf(mx2, s2);
            }
        }
        mx1 = fmaxf(mx1, __shfl_xor_sync(0xffffffffu, mx1, 1));
        mx1 = fmaxf(mx1, __shfl_xor_sync(0xffffffffu, mx1, 2));
        mx2 = fmaxf(mx2, __shfl_xor_sync(0xffffffffu, mx2, 1));
        mx2 = fmaxf(mx2, __shfl_xor_sync(0xffffffffu, mx2, 2));

        float sum1 = 0.f, sum2 = 0.f;
#pragma unroll
        for (int nt = 0; nt < NT; nt++) {
#pragma unroll
            for (int t = 0; t < 2; t++) {
                float e1 = __expf(acc[nt][t] - mx1);
                float e2 = __expf(acc[nt][2 + t] - mx2);
                acc[nt][t] = e1;
                acc[nt][2 + t] = e2;
                sum1 += e1;
                sum2 += e2;
            }
        }
        sum1 += __shfl_xor_sync(0xffffffffu, sum1, 1);
        sum1 += __shfl_xor_sync(0xffffffffu, sum1, 2);
        sum2 += __shfl_xor_sync(0xffffffffu, sum2, 1);
        sum2 += __shfl_xor_sync(0xffffffffu, sum2, 2);
        float inv1 = 1.f / sum1;
        float inv2 = 1.f / sum2;

        // ---- O(16 x 64) = P @ V ; P frags packed from own accumulator ----
        float ao[8][4];
#pragma unroll
        for (int nt = 0; nt < 8; nt++)
#pragma unroll
            for (int t = 0; t < 4; t++) ao[nt][t] = 0.f;

#pragma unroll
        for (int ks = 0; ks < 13; ks++) {
            uint32_t pa[4];
            pa[0] = packh2(acc[2 * ks][0], acc[2 * ks][1]);
            pa[1] = packh2(acc[2 * ks][2], acc[2 * ks][3]);
            pa[2] = packh2(acc[2 * ks + 1][0], acc[2 * ks + 1][1]);
            pa[3] = packh2(acc[2 * ks + 1][2], acc[2 * ks + 1][3]);
#pragma unroll
            for (int nt = 0; nt < 8; nt++) {
                int nr = nt * 8 + lq;
                uint32_t b0 = Vw[nr * VTS_W + 8 * ks + lr];
                uint32_t b1 = Vw[nr * VTS_W + 8 * ks + 4 + lr];
                mma_f16(ao[nt], pa, b0, b1);
            }
        }

        // ---- write O, normalizing ----
#pragma unroll
        for (int nt = 0; nt < 8; nt++) {
            int c = nt * 8 + lr * 2;
            if (r1 < SEQ)
                *(float2*)&og[(size_t)(b * SEQ + r1) * DIM + h * HEAD_DIM + c] =
                    make_float2(ao[nt][0] * inv1, ao[nt][1] * inv1);
            if (r2 < SEQ)
                *(float2*)&og[(size_t)(b * SEQ + r2) * DIM + h * HEAD_DIM + c] =
                    make_float2(ao[nt][2] * inv2, ao[nt][3] * inv2);
        }
    }
}

// ---------------- launch ----------------
extern "C" void kernel_launch(void* const* d_in, const int* in_sizes, int n_in,
                              void* d_out, int out_size)
{
    const float* x      = (const float*)d_in[0];
    const float* qk_w   = (const float*)d_in[1];
    const float* v_w    = (const float*)d_in[2];
    const float* w1_w   = (const float*)d_in[3];
    const float* w1_b   = (const float*)d_in[4];
    const float* w2     = (const float*)d_in[5];
    const float* b2     = (const float*)d_in[6];
    const float* proj_w = (const float*)d_in[7];
    const float* proj_b = (const float*)d_in[8];
    float* out = (float*)d_out;

    float *qk_buf, *v_buf, *o_buf, *pos_buf;
    cudaGetSymbolAddress((void**)&qk_buf, g_qk);
    cudaGetSymbolAddress((void**)&v_buf, g_v);
    cudaGetSymbolAddress((void**)&o_buf, g_o);
    cudaGetSymbolAddress((void**)&pos_buf, g_pos);

    pos_kernel<<<729, 384>>>(w1_w, w1_b, w2, b2, pos_buf);

    // qk projection: (12544,1536)
    {
        dim3 grid(2 * DIM / 128, MTOT / 128);
        gemm_f16<<<grid, 256>>>(x, qk_w, nullptr, qk_buf, MTOT, 2 * DIM, DIM);
    }
    // v projection: (12544,768)
    {
        dim3 grid(DIM / 128, MTOT / 128);
        gemm_f16<<<grid, 256>>>(x, v_w, nullptr, v_buf, MTOT, DIM, DIM);
    }
    // fused attention
    {
        int smem_bytes = ATTN_SM_WORDS * 4;
        cudaFuncSetAttribute(attn_mma, cudaFuncAttributeMaxDynamicSharedMemorySize, smem_bytes);
        attn_mma<<<BATCH * HEADS, 256, smem_bytes>>>(qk_buf, v_buf, pos_buf, o_buf);
    }
    // output projection with bias
    {
        dim3 grid(DIM / 128, MTOT / 128);
        gemm_f16<<<grid, 256>>>(o_buf, proj_w, proj_b, out, MTOT, DIM, DIM);
    }
}

// round 9
// speedup vs baseline: 5.8959x; 1.2074x over previous
#include <cuda_runtime.h>
#include <cuda_fp16.h>
#include <math.h>
#include <stdint.h>

#define DIM 768
#define HEADS 12
#define HEAD_DIM 64
#define BATCH 64
#define SEQ 196
#define MTOT (BATCH * SEQ)      // 12544
#define SCALE 0.125f

// ---------------- scratch ----------------
__device__ float g_qk[(size_t)MTOT * 2 * DIM];
__device__ float g_v[(size_t)MTOT * DIM];
__device__ float g_o[(size_t)MTOT * DIM];
__device__ float g_pos[HEADS * 729];

// ---------------- helpers ----------------
__device__ __forceinline__ uint32_t packh2(float x, float y) {
    __half2 h = __floats2half2_rn(x, y);
    return *(uint32_t*)&h;
}

__device__ __forceinline__ void mma_f16(float* c, const uint32_t* a, uint32_t b0, uint32_t b1) {
    asm volatile(
        "mma.sync.aligned.m16n8k16.row.col.f32.f16.f16.f32 "
        "{%0,%1,%2,%3}, {%4,%5,%6,%7}, {%8,%9}, {%0,%1,%2,%3};\n"
        : "+f"(c[0]), "+f"(c[1]), "+f"(c[2]), "+f"(c[3])
        : "r"(a[0]), "r"(a[1]), "r"(a[2]), "r"(a[3]), "r"(b0), "r"(b1));
}

// ---------------- pos table ----------------
__global__ void pos_kernel(const float* __restrict__ w1,
                           const float* __restrict__ b1,
                           const float* __restrict__ w2,
                           const float* __restrict__ b2,
                           float* __restrict__ out)
{
    int c = blockIdx.x;
    float dx = (float)(c % 27 - 13);
    float dy = (float)(c / 27 - 13);
    int h = threadIdx.x >> 5;
    int lane = threadIdx.x & 31;
    float sum = 0.f;
#pragma unroll
    for (int mm = lane; mm < HEAD_DIM; mm += 32) {
        int g = h * HEAD_DIM + mm;
        float t = fmaf(dx, w1[g * 2 + 0], fmaf(dy, w1[g * 2 + 1], b1[g]));
        t = fmaxf(t, 0.f);
        sum += t * w2[g];
    }
#pragma unroll
    for (int o = 16; o > 0; o >>= 1) sum += __shfl_xor_sync(0xffffffffu, sum, o);
    if (lane == 0) out[h * 729 + c] = sum + b2[h];
}

// ---------------- FP16 tensor-core GEMM, register-prefetch pipelined ----------------
#define GSTRW 20   // words per smem row (32 halves data + 8 pad)

__global__ __launch_bounds__(256, 2)
void gemm_f16(const float* __restrict__ A, const float* __restrict__ B,
              const float* __restrict__ bias, float* __restrict__ C,
              int M, int N, int K)
{
    __shared__ uint32_t As[128 * GSTRW];
    __shared__ uint32_t Bs[128 * GSTRW];

    int tid = threadIdx.x;
    int lane = tid & 31;
    int w = tid >> 5;
    int wm = w >> 2;            // 0..1
    int wn = w & 3;             // 0..3
    int lq = lane >> 2;         // 0..7
    int lr = lane & 3;          // 0..3
    int m0 = blockIdx.y * 128;
    int n0 = blockIdx.x * 128;

    int lrow = tid >> 3;        // 0..31
    int lf4 = tid & 7;          // 0..7

    float acc[4][4][4];
#pragma unroll
    for (int i = 0; i < 4; i++)
#pragma unroll
        for (int j = 0; j < 4; j++)
#pragma unroll
            for (int t = 0; t < 4; t++) acc[i][j][t] = 0.f;

    float4 pa[4], pb[4];
    // initial load (k0 = 0)
#pragma unroll
    for (int p = 0; p < 4; p++) {
        int row = lrow + p * 32;
        pa[p] = *(const float4*)&A[(size_t)(m0 + row) * K + lf4 * 4];
        pb[p] = *(const float4*)&B[(size_t)(n0 + row) * K + lf4 * 4];
    }

    for (int k0 = 0; k0 < K; k0 += 32) {
        // store prefetched tile to smem (pack fp32 -> half2)
#pragma unroll
        for (int p = 0; p < 4; p++) {
            int row = lrow + p * 32;
            uint2 ap;
            ap.x = packh2(pa[p].x, pa[p].y);
            ap.y = packh2(pa[p].z, pa[p].w);
            *(uint2*)&As[row * GSTRW + lf4 * 2] = ap;
            uint2 bp;
            bp.x = packh2(pb[p].x, pb[p].y);
            bp.y = packh2(pb[p].z, pb[p].w);
            *(uint2*)&Bs[row * GSTRW + lf4 * 2] = bp;
        }
        __syncthreads();

        // prefetch next k-tile (overlaps with MMA phase)
        if (k0 + 32 < K) {
#pragma unroll
            for (int p = 0; p < 4; p++) {
                int row = lrow + p * 32;
                pa[p] = *(const float4*)&A[(size_t)(m0 + row) * K + k0 + 32 + lf4 * 4];
                pb[p] = *(const float4*)&B[(size_t)(n0 + row) * K + k0 + 32 + lf4 * 4];
            }
        }

#pragma unroll
        for (int ks = 0; ks < 2; ks++) {
            int kb2 = ks * 8;
            uint32_t af[4][4], bf[4][2];
#pragma unroll
            for (int i = 0; i < 4; i++) {
                int r = wm * 64 + i * 16 + lq;
                af[i][0] = As[r * GSTRW + kb2 + lr];
                af[i][1] = As[(r + 8) * GSTRW + kb2 + lr];
                af[i][2] = As[r * GSTRW + kb2 + 4 + lr];
                af[i][3] = As[(r + 8) * GSTRW + kb2 + 4 + lr];
            }
#pragma unroll
            for (int j = 0; j < 4; j++) {
                int n = wn * 32 + j * 8 + lq;
                bf[j][0] = Bs[n * GSTRW + kb2 + lr];
                bf[j][1] = Bs[n * GSTRW + kb2 + 4 + lr];
            }
#pragma unroll
            for (int i = 0; i < 4; i++)
#pragma unroll
                for (int j = 0; j < 4; j++)
                    mma_f16(acc[i][j], af[i], bf[j][0], bf[j][1]);
        }
        __syncthreads();
    }

#pragma unroll
    for (int i = 0; i < 4; i++) {
#pragma unroll
        for (int j = 0; j < 4; j++) {
            int row = m0 + wm * 64 + i * 16 + lq;
            int col = n0 + wn * 32 + j * 8 + lr * 2;
            float b0 = bias ? bias[col] : 0.f;
            float b1 = bias ? bias[col + 1] : 0.f;
            *(float2*)&C[(size_t)row * N + col] =
                make_float2(acc[i][j][0] + b0, acc[i][j][1] + b1);
            *(float2*)&C[(size_t)(row + 8) * N + col] =
                make_float2(acc[i][j][2] + b0, acc[i][j][3] + b1);
        }
    }
}

// ---------------- FP16 MMA attention, chunked (2 x 112 cols), no-max softmax ----
// Scores here are bounded (|s| ~ 4), so exp() without max subtraction is safe
// and mathematically identical after normalization.
// smem: K [224][72 halves], Vt [64][232 halves], pos[729] f32, colcode[224].
#define KSH_W 36            // words per K row (72 halves)
#define VTS_W 116           // words per Vt row (232 halves)
#define NPAD 224
#define CNT 14              // n-tiles per chunk (112 cols)
#define ATTN_SM_WORDS (NPAD * KSH_W + 64 * VTS_W + 729 + NPAD)

__global__ __launch_bounds__(256, 2)
void attn_mma(const float* __restrict__ qk,
              const float* __restrict__ v,
              const float* __restrict__ pos,
              float* __restrict__ og)
{
    extern __shared__ uint32_t smu[];
    uint32_t* Kw   = smu;                        // [224][36] words
    uint32_t* Vw   = Kw + NPAD * KSH_W;          // [64][116] words
    float*    posh = (float*)(Vw + 64 * VTS_W);  // 729
    int*      colc = (int*)(posh + 729);         // 224

    int bh = blockIdx.x;
    int b = bh / HEADS;
    int h = bh % HEADS;
    int tid = threadIdx.x;
    int w = tid >> 5;
    int lane = tid & 31;
    int lq = lane >> 2;       // 0..7
    int lr = lane & 3;        // 0..3

    // ---- zero pads: K rows 196..223, Vt col words 98..115 ----
    for (int idx = tid; idx < 28 * KSH_W; idx += 256)
        Kw[196 * KSH_W + idx] = 0;
    for (int idx = tid; idx < 64 * 18; idx += 256) {
        int d = idx / 18, wz = 98 + idx % 18;
        Vw[d * VTS_W + wz] = 0;
    }

    // ---- stage K rows 0..195 ----
    for (int idx = tid; idx < SEQ * 16; idx += 256) {
        int j = idx >> 4, d4 = idx & 15;
        float4 val = *(const float4*)&qk[(size_t)(b * SEQ + j) * (2 * DIM) + DIM + h * HEAD_DIM + d4 * 4];
        uint2 p;
        p.x = packh2(val.x, val.y);
        p.y = packh2(val.z, val.w);
        *(uint2*)&Kw[j * KSH_W + d4 * 2] = p;
    }
    // ---- stage V transposed ----
    {
        __half* Vh = (__half*)Vw;
        for (int idx = tid; idx < SEQ * 16; idx += 256) {
            int j = idx >> 4, d4 = idx & 15;
            float4 val = *(const float4*)&v[(size_t)(b * SEQ + j) * DIM + h * HEAD_DIM + d4 * 4];
            Vh[(d4 * 4 + 0) * (VTS_W * 2) + j] = __float2half(val.x);
            Vh[(d4 * 4 + 1) * (VTS_W * 2) + j] = __float2half(val.y);
            Vh[(d4 * 4 + 2) * (VTS_W * 2) + j] = __float2half(val.z);
            Vh[(d4 * 4 + 3) * (VTS_W * 2) + j] = __float2half(val.w);
        }
    }
    for (int c = tid; c < 729; c += 256) posh[c] = pos[h * 729 + c];
    for (int c = tid; c < NPAD; c += 256) {
        int cc = c > 195 ? 195 : c;
        colc[c] = (cc / 14) * 27 + (cc % 14);
    }
    __syncthreads();

    for (int mt = w; mt < 13; mt += 8) {
        int m0 = mt * 16;
        int r1 = m0 + lq, r2 = r1 + 8;
        int r1c = r1 > 195 ? 195 : r1;
        int r2c = r2 > 195 ? 195 : r2;
        const float* q1 = &qk[(size_t)(b * SEQ + r1c) * (2 * DIM) + h * HEAD_DIM];
        const float* q2 = &qk[(size_t)(b * SEQ + r2c) * (2 * DIM) + h * HEAD_DIM];

        // ---- Q fragments direct from global ----
        uint32_t af[4][4];
#pragma unroll
        for (int ks = 0; ks < 4; ks++) {
            float2 t;
            t = *(const float2*)&q1[16 * ks + 2 * lr];
            af[ks][0] = packh2(t.x, t.y);
            t = *(const float2*)&q2[16 * ks + 2 * lr];
            af[ks][1] = packh2(t.x, t.y);
            t = *(const float2*)&q1[16 * ks + 8 + 2 * lr];
            af[ks][2] = packh2(t.x, t.y);
            t = *(const float2*)&q2[16 * ks + 8 + 2 * lr];
            af[ks][3] = packh2(t.x, t.y);
        }

        int base1 = (13 - r1c / 14) * 27 + (13 - r1c % 14);
        int base2 = (13 - r2c / 14) * 27 + (13 - r2c % 14);

        float ao[8][4];
#pragma unroll
        for (int nt = 0; nt < 8; nt++)
#pragma unroll
            for (int t = 0; t < 4; t++) ao[nt][t] = 0.f;
        float sum1 = 0.f, sum2 = 0.f;

#pragma unroll
        for (int ch = 0; ch < 2; ch++) {
            // ---- S chunk (16 x 112) ----
            float acc[CNT][4];
#pragma unroll
            for (int nt = 0; nt < CNT; nt++)
#pragma unroll
                for (int t = 0; t < 4; t++) acc[nt][t] = 0.f;

#pragma unroll
            for (int ks = 0; ks < 4; ks++) {
#pragma unroll
                for (int nt = 0; nt < CNT; nt++) {
                    int nr = (ch * CNT + nt) * 8 + lq;
                    uint32_t b0 = Kw[nr * KSH_W + 8 * ks + lr];
                    uint32_t b1 = Kw[nr * KSH_W + 8 * ks + 4 + lr];
                    mma_f16(acc[nt], af[ks], b0, b1);
                }
            }

            // ---- exp(scale * pos * s), masked; accumulate row sums ----
#pragma unroll
            for (int nt = 0; nt < CNT; nt++) {
#pragma unroll
                for (int t = 0; t < 2; t++) {
                    int c = ch * 112 + nt * 8 + lr * 2 + t;
                    int code = colc[c];
                    float p1 = posh[code + base1];
                    float p2 = posh[code + base2];
                    float e1 = __expf(acc[nt][t] * SCALE * p1);
                    float e2 = __expf(acc[nt][2 + t] * SCALE * p2);
                    if (c > 195) { e1 = 0.f; e2 = 0.f; }
                    acc[nt][t] = e1;
                    acc[nt][2 + t] = e2;
                    sum1 += e1;
                    sum2 += e2;
                }
            }

            // ---- PV chunk: O += P_chunk @ V_chunk ----
#pragma unroll
            for (int ks = 0; ks < 7; ks++) {
                uint32_t pa[4];
                pa[0] = packh2(acc[2 * ks][0], acc[2 * ks][1]);
                pa[1] = packh2(acc[2 * ks][2], acc[2 * ks][3]);
                pa[2] = packh2(acc[2 * ks + 1][0], acc[2 * ks + 1][1]);
                pa[3] = packh2(acc[2 * ks + 1][2], acc[2 * ks + 1][3]);
#pragma unroll
                for (int nt = 0; nt < 8; nt++) {
                    int nr = nt * 8 + lq;
                    uint32_t b0 = Vw[nr * VTS_W + 8 * (ch * 7 + ks) + lr];
                    uint32_t b1 = Vw[nr * VTS_W + 8 * (ch * 7 + ks) + 4 + lr];
                    mma_f16(ao[nt], pa, b0, b1);
                }
            }
        }

        // quad-reduce row sums (lanes lr 0..3 hold partial cols of same rows)
        sum1 += __shfl_xor_sync(0xffffffffu, sum1, 1);
        sum1 += __shfl_xor_sync(0xffffffffu, sum1, 2);
        sum2 += __shfl_xor_sync(0xffffffffu, sum2, 1);
        sum2 += __shfl_xor_sync(0xffffffffu, sum2, 2);
        float inv1 = 1.f / sum1;
        float inv2 = 1.f / sum2;

        // ---- write O ----
#pragma unroll
        for (int nt = 0; nt < 8; nt++) {
            int c = nt * 8 + lr * 2;
            if (r1 < SEQ)
                *(float2*)&og[(size_t)(b * SEQ + r1) * DIM + h * HEAD_DIM + c] =
                    make_float2(ao[nt][0] * inv1, ao[nt][1] * inv1);
            if (r2 < SEQ)
                *(float2*)&og[(size_t)(b * SEQ + r2) * DIM + h * HEAD_DIM + c] =
                    make_float2(ao[nt][2] * inv2, ao[nt][3] * inv2);
        }
    }
}

// ---------------- launch ----------------
extern "C" void kernel_launch(void* const* d_in, const int* in_sizes, int n_in,
                              void* d_out, int out_size)
{
    const float* x      = (const float*)d_in[0];
    const float* qk_w   = (const float*)d_in[1];
    const float* v_w    = (const float*)d_in[2];
    const float* w1_w   = (const float*)d_in[3];
    const float* w1_b   = (const float*)d_in[4];
    const float* w2     = (const float*)d_in[5];
    const float* b2     = (const float*)d_in[6];
    const float* proj_w = (const float*)d_in[7];
    const float* proj_b = (const float*)d_in[8];
    float* out = (float*)d_out;

    float *qk_buf, *v_buf, *o_buf, *pos_buf;
    cudaGetSymbolAddress((void**)&qk_buf, g_qk);
    cudaGetSymbolAddress((void**)&v_buf, g_v);
    cudaGetSymbolAddress((void**)&o_buf, g_o);
    cudaGetSymbolAddress((void**)&pos_buf, g_pos);

    pos_kernel<<<729, 384>>>(w1_w, w1_b, w2, b2, pos_buf);

    // qk projection: (12544,1536)
    {
        dim3 grid(2 * DIM / 128, MTOT / 128);
        gemm_f16<<<grid, 256>>>(x, qk_w, nullptr, qk_buf, MTOT, 2 * DIM, DIM);
    }
    // v projection: (12544,768)
    {
        dim3 grid(DIM / 128, MTOT / 128);
        gemm_f16<<<grid, 256>>>(x, v_w, nullptr, v_buf, MTOT, DIM, DIM);
    }
    // fused attention
    {
        int smem_bytes = ATTN_SM_WORDS * 4;
        cudaFuncSetAttribute(attn_mma, cudaFuncAttributeMaxDynamicSharedMemorySize, smem_bytes);
        attn_mma<<<BATCH * HEADS, 256, smem_bytes>>>(qk_buf, v_buf, pos_buf, o_buf);
    }
    // output projection with bias
    {
        dim3 grid(DIM / 128, MTOT / 128);
        gemm_f16<<<grid, 256>>>(o_buf, proj_w, proj_b, out, MTOT, DIM, DIM);
    }
}

// round 10
// speedup vs baseline: 7.1334x; 1.2099x over previous
#include <cuda_runtime.h>
#include <cuda_fp16.h>
#include <math.h>
#include <stdint.h>

#define DIM 768
#define HEADS 12
#define HEAD_DIM 64
#define BATCH 64
#define SEQ 196
#define MTOT (BATCH * SEQ)      // 12544
#define SCALE 0.125f

// ---------------- scratch (all fp16 intermediates) ----------------
__device__ __half gx_h[(size_t)MTOT * DIM];
__device__ __half gqk_h[(size_t)MTOT * 2 * DIM];
__device__ __half gv_h[(size_t)MTOT * DIM];
__device__ __half go_h[(size_t)MTOT * DIM];
__device__ __half gqkw_h[2 * DIM * DIM];
__device__ __half gvw_h[DIM * DIM];
__device__ __half gpw_h[DIM * DIM];
__device__ float g_pos[HEADS * 729];

// ---------------- helpers ----------------
__device__ __forceinline__ uint32_t packh2(float x, float y) {
    __half2 h = __floats2half2_rn(x, y);
    return *(uint32_t*)&h;
}

__device__ __forceinline__ void mma_f16(float* c, const uint32_t* a, uint32_t b0, uint32_t b1) {
    asm volatile(
        "mma.sync.aligned.m16n8k16.row.col.f32.f16.f16.f32 "
        "{%0,%1,%2,%3}, {%4,%5,%6,%7}, {%8,%9}, {%0,%1,%2,%3};\n"
        : "+f"(c[0]), "+f"(c[1]), "+f"(c[2]), "+f"(c[3])
        : "r"(a[0]), "r"(a[1]), "r"(a[2]), "r"(a[3]), "r"(b0), "r"(b1));
}

__device__ __forceinline__ uint32_t smem_u32(const void* p) {
    uint32_t a;
    asm("{ .reg .u64 t; cvta.to.shared.u64 t, %1; cvt.u32.u64 %0, t; }" : "=r"(a) : "l"(p));
    return a;
}

#define CP_ASYNC16(smaddr, gptr) \
    asm volatile("cp.async.cg.shared.global [%0], [%1], 16;" :: "r"(smaddr), "l"(gptr) : "memory")
#define CP_COMMIT() asm volatile("cp.async.commit_group;" ::: "memory")
#define CP_WAIT(n)  asm volatile("cp.async.wait_group %0;" :: "n"(n) : "memory")

// ---------------- fp32 -> fp16 convert ----------------
__global__ void conv_h(const float* __restrict__ src, __half* __restrict__ dst, int n) {
    int i = (blockIdx.x * 256 + threadIdx.x) * 4;
    if (i < n) {
        float4 v = *(const float4*)&src[i];
        uint2 p;
        p.x = packh2(v.x, v.y);
        p.y = packh2(v.z, v.w);
        *(uint2*)&dst[i] = p;
    }
}

// ---------------- pos table ----------------
__global__ void pos_kernel(const float* __restrict__ w1,
                           const float* __restrict__ b1,
                           const float* __restrict__ w2,
                           const float* __restrict__ b2,
                           float* __restrict__ out)
{
    int c = blockIdx.x;
    float dx = (float)(c % 27 - 13);
    float dy = (float)(c / 27 - 13);
    int h = threadIdx.x >> 5;
    int lane = threadIdx.x & 31;
    float sum = 0.f;
#pragma unroll
    for (int mm = lane; mm < HEAD_DIM; mm += 32) {
        int g = h * HEAD_DIM + mm;
        float t = fmaf(dx, w1[g * 2 + 0], fmaf(dy, w1[g * 2 + 1], b1[g]));
        t = fmaxf(t, 0.f);
        sum += t * w2[g];
    }
#pragma unroll
    for (int o = 16; o > 0; o >>= 1) sum += __shfl_xor_sync(0xffffffffu, sum, o);
    if (lane == 0) out[h * 729 + c] = sum + b2[h];
}

// ---------------- pure-fp16 GEMM, cp.async double-buffered, BK=64 ----------------
// C[m][n] = sum_k A[m][k]*B[n][k] (+ bias[n]). A,B half. C half or float.
// smem row: 64 halves + 8 pad = 36 words. Buffer = (A 128 + B 128) rows.
#define HSTRW 36
#define HBUF_W (2 * 128 * HSTRW)    // words per buffer (A then B)
#define HSM_BYTES (2 * HBUF_W * 4)  // 73728

template <bool OUT_FLOAT>
__global__ __launch_bounds__(256, 2)
void gemm_h(const __half* __restrict__ A, const __half* __restrict__ B,
            const float* __restrict__ bias, void* __restrict__ Cout,
            int M, int N, int K)
{
    extern __shared__ uint32_t sm[];

    int tid = threadIdx.x;
    int lane = tid & 31;
    int w = tid >> 5;
    int wm = w >> 2;            // 0..1
    int wn = w & 3;             // 0..3
    int lq = lane >> 2;         // 0..7
    int lr = lane & 3;          // 0..3
    int m0 = blockIdx.y * 128;
    int n0 = blockIdx.x * 128;

    float acc[4][4][4];
#pragma unroll
    for (int i = 0; i < 4; i++)
#pragma unroll
        for (int j = 0; j < 4; j++)
#pragma unroll
            for (int t = 0; t < 4; t++) acc[i][j][t] = 0.f;

    uint32_t smb = smem_u32(sm);
    int NT_K = K / 64;

    // chunk mapping: c = tid + i*256 (0..1023): row = c>>3, c8 = c&7 (16B units)
    auto issue = [&](int buf, int k0) {
#pragma unroll
        for (int i = 0; i < 4; i++) {
            int c = tid + i * 256;
            int row = c >> 3, c8 = c & 7;
            uint32_t dstA = smb + (buf * HBUF_W + row * HSTRW + c8 * 4) * 4;
            CP_ASYNC16(dstA, A + (size_t)(m0 + row) * K + k0 + c8 * 8);
            uint32_t dstB = smb + (buf * HBUF_W + (128 + row) * HSTRW + c8 * 4) * 4;
            CP_ASYNC16(dstB, B + (size_t)(n0 + row) * K + k0 + c8 * 8);
        }
        CP_COMMIT();
    };

    issue(0, 0);

    for (int kt = 0; kt < NT_K; kt++) {
        if (kt + 1 < NT_K) {
            issue((kt + 1) & 1, (kt + 1) * 64);
            CP_WAIT(1);
        } else {
            CP_WAIT(0);
        }
        __syncthreads();

        const uint32_t* As = sm + (kt & 1) * HBUF_W;
        const uint32_t* Bs = As + 128 * HSTRW;

#pragma unroll
        for (int ks = 0; ks < 4; ks++) {
            int kb = ks * 8;
            uint32_t af[4][4], bf[4][2];
#pragma unroll
            for (int i = 0; i < 4; i++) {
                int r = wm * 64 + i * 16 + lq;
                af[i][0] = As[r * HSTRW + kb + lr];
                af[i][1] = As[(r + 8) * HSTRW + kb + lr];
                af[i][2] = As[r * HSTRW + kb + 4 + lr];
                af[i][3] = As[(r + 8) * HSTRW + kb + 4 + lr];
            }
#pragma unroll
            for (int j = 0; j < 4; j++) {
                int n = wn * 32 + j * 8 + lq;
                bf[j][0] = Bs[n * HSTRW + kb + lr];
                bf[j][1] = Bs[n * HSTRW + kb + 4 + lr];
            }
#pragma unroll
            for (int i = 0; i < 4; i++)
#pragma unroll
                for (int j = 0; j < 4; j++)
                    mma_f16(acc[i][j], af[i], bf[j][0], bf[j][1]);
        }
        __syncthreads();
    }

#pragma unroll
    for (int i = 0; i < 4; i++) {
#pragma unroll
        for (int j = 0; j < 4; j++) {
            int row = m0 + wm * 64 + i * 16 + lq;
            int col = n0 + wn * 32 + j * 8 + lr * 2;
            float b0 = bias ? bias[col] : 0.f;
            float b1 = bias ? bias[col + 1] : 0.f;
            if (OUT_FLOAT) {
                float* C = (float*)Cout;
                *(float2*)&C[(size_t)row * N + col] =
                    make_float2(acc[i][j][0] + b0, acc[i][j][1] + b1);
                *(float2*)&C[(size_t)(row + 8) * N + col] =
                    make_float2(acc[i][j][2] + b0, acc[i][j][3] + b1);
            } else {
                __half* C = (__half*)Cout;
                *(uint32_t*)&C[(size_t)row * N + col] = packh2(acc[i][j][0] + b0, acc[i][j][1] + b1);
                *(uint32_t*)&C[(size_t)(row + 8) * N + col] = packh2(acc[i][j][2] + b0, acc[i][j][3] + b1);
            }
        }
    }
}

// ---------------- FP16 MMA attention (inputs/outputs fp16) ----------------
#define KSH_W 36            // words per K row (72 halves)
#define VTS_W 116           // words per Vt row (232 halves)
#define NPAD 224
#define CNT 14
#define ATTN_SM_WORDS (NPAD * KSH_W + 64 * VTS_W + 729 + NPAD)

__global__ __launch_bounds__(256, 2)
void attn_mma(const __half* __restrict__ qk,
              const __half* __restrict__ v,
              const float* __restrict__ pos,
              __half* __restrict__ og)
{
    extern __shared__ uint32_t smu[];
    uint32_t* Kw   = smu;                        // [224][36] words
    uint32_t* Vw   = Kw + NPAD * KSH_W;          // [64][116] words
    float*    posh = (float*)(Vw + 64 * VTS_W);  // 729
    int*      colc = (int*)(posh + 729);         // 224

    int bh = blockIdx.x;
    int b = bh / HEADS;
    int h = bh % HEADS;
    int tid = threadIdx.x;
    int w = tid >> 5;
    int lane = tid & 31;
    int lq = lane >> 2;
    int lr = lane & 3;

    // zero pads: K rows 196..223, Vt col words 98..115
    for (int idx = tid; idx < 28 * KSH_W; idx += 256)
        Kw[196 * KSH_W + idx] = 0;
    for (int idx = tid; idx < 64 * 18; idx += 256) {
        int d = idx / 18, wz = 98 + idx % 18;
        Vw[d * VTS_W + wz] = 0;
    }

    // stage K rows 0..195 (pure uint4 copies; half pairs already packed)
    for (int idx = tid; idx < SEQ * 8; idx += 256) {
        int j = idx >> 3, c8 = idx & 7;
        *(uint4*)&Kw[j * KSH_W + c8 * 4] =
            *(const uint4*)&qk[(size_t)(b * SEQ + j) * (2 * DIM) + DIM + h * HEAD_DIM + c8 * 8];
    }
    // stage V transposed
    {
        __half* Vh = (__half*)Vw;
        for (int idx = tid; idx < SEQ * 8; idx += 256) {
            int j = idx >> 3, d8 = (idx & 7) * 8;
            uint4 val = *(const uint4*)&v[(size_t)(b * SEQ + j) * DIM + h * HEAD_DIM + d8];
            const __half* hv = (const __half*)&val;
#pragma unroll
            for (int t = 0; t < 8; t++)
                Vh[(d8 + t) * (VTS_W * 2) + j] = hv[t];
        }
    }
    for (int c = tid; c < 729; c += 256) posh[c] = pos[h * 729 + c];
    for (int c = tid; c < NPAD; c += 256) {
        int cc = c > 195 ? 195 : c;
        colc[c] = (cc / 14) * 27 + (cc % 14);
    }
    __syncthreads();

    for (int mt = w; mt < 13; mt += 8) {
        int m0 = mt * 16;
        int r1 = m0 + lq, r2 = r1 + 8;
        int r1c = r1 > 195 ? 195 : r1;
        int r2c = r2 > 195 ? 195 : r2;
        const __half* q1 = &qk[(size_t)(b * SEQ + r1c) * (2 * DIM) + h * HEAD_DIM];
        const __half* q2 = &qk[(size_t)(b * SEQ + r2c) * (2 * DIM) + h * HEAD_DIM];

        // Q fragments: direct half2 loads
        uint32_t af[4][4];
#pragma unroll
        for (int ks = 0; ks < 4; ks++) {
            af[ks][0] = *(const uint32_t*)&q1[16 * ks + 2 * lr];
            af[ks][1] = *(const uint32_t*)&q2[16 * ks + 2 * lr];
            af[ks][2] = *(const uint32_t*)&q1[16 * ks + 8 + 2 * lr];
            af[ks][3] = *(const uint32_t*)&q2[16 * ks + 8 + 2 * lr];
        }

        int base1 = (13 - r1c / 14) * 27 + (13 - r1c % 14);
        int base2 = (13 - r2c / 14) * 27 + (13 - r2c % 14);

        float ao[8][4];
#pragma unroll
        for (int nt = 0; nt < 8; nt++)
#pragma unroll
            for (int t = 0; t < 4; t++) ao[nt][t] = 0.f;
        float sum1 = 0.f, sum2 = 0.f;

#pragma unroll
        for (int ch = 0; ch < 2; ch++) {
            float acc[CNT][4];
#pragma unroll
            for (int nt = 0; nt < CNT; nt++)
#pragma unroll
                for (int t = 0; t < 4; t++) acc[nt][t] = 0.f;

#pragma unroll
            for (int ks = 0; ks < 4; ks++) {
#pragma unroll
                for (int nt = 0; nt < CNT; nt++) {
                    int nr = (ch * CNT + nt) * 8 + lq;
                    uint32_t b0 = Kw[nr * KSH_W + 8 * ks + lr];
                    uint32_t b1 = Kw[nr * KSH_W + 8 * ks + 4 + lr];
                    mma_f16(acc[nt], af[ks], b0, b1);
                }
            }

#pragma unroll
            for (int nt = 0; nt < CNT; nt++) {
#pragma unroll
                for (int t = 0; t < 2; t++) {
                    int c = ch * 112 + nt * 8 + lr * 2 + t;
                    int code = colc[c];
                    float p1 = posh[code + base1];
                    float p2 = posh[code + base2];
                    float e1 = __expf(acc[nt][t] * SCALE * p1);
                    float e2 = __expf(acc[nt][2 + t] * SCALE * p2);
                    if (c > 195) { e1 = 0.f; e2 = 0.f; }
                    acc[nt][t] = e1;
                    acc[nt][2 + t] = e2;
                    sum1 += e1;
                    sum2 += e2;
                }
            }

#pragma unroll
            for (int ks = 0; ks < 7; ks++) {
                uint32_t pa[4];
                pa[0] = packh2(acc[2 * ks][0], acc[2 * ks][1]);
                pa[1] = packh2(acc[2 * ks][2], acc[2 * ks][3]);
                pa[2] = packh2(acc[2 * ks + 1][0], acc[2 * ks + 1][1]);
                pa[3] = packh2(acc[2 * ks + 1][2], acc[2 * ks + 1][3]);
#pragma unroll
                for (int nt = 0; nt < 8; nt++) {
                    int nr = nt * 8 + lq;
                    uint32_t b0 = Vw[nr * VTS_W + 8 * (ch * 7 + ks) + lr];
                    uint32_t b1 = Vw[nr * VTS_W + 8 * (ch * 7 + ks) + 4 + lr];
                    mma_f16(ao[nt], pa, b0, b1);
                }
            }
        }

        sum1 += __shfl_xor_sync(0xffffffffu, sum1, 1);
        sum1 += __shfl_xor_sync(0xffffffffu, sum1, 2);
        sum2 += __shfl_xor_sync(0xffffffffu, sum2, 1);
        sum2 += __shfl_xor_sync(0xffffffffu, sum2, 2);
        float inv1 = 1.f / sum1;
        float inv2 = 1.f / sum2;

#pragma unroll
        for (int nt = 0; nt < 8; nt++) {
            int c = nt * 8 + lr * 2;
            if (r1 < SEQ)
                *(uint32_t*)&og[(size_t)(b * SEQ + r1) * DIM + h * HEAD_DIM + c] =
                    packh2(ao[nt][0] * inv1, ao[nt][1] * inv1);
            if (r2 < SEQ)
                *(uint32_t*)&og[(size_t)(b * SEQ + r2) * DIM + h * HEAD_DIM + c] =
                    packh2(ao[nt][2] * inv2, ao[nt][3] * inv2);
        }
    }
}

// ---------------- launch ----------------
extern "C" void kernel_launch(void* const* d_in, const int* in_sizes, int n_in,
                              void* d_out, int out_size)
{
    const float* x      = (const float*)d_in[0];
    const float* qk_w   = (const float*)d_in[1];
    const float* v_w    = (const float*)d_in[2];
    const float* w1_w   = (const float*)d_in[3];
    const float* w1_b   = (const float*)d_in[4];
    const float* w2     = (const float*)d_in[5];
    const float* b2     = (const float*)d_in[6];
    const float* proj_w = (const float*)d_in[7];
    const float* proj_b = (const float*)d_in[8];
    float* out = (float*)d_out;

    __half *xh, *qkh, *vh, *oh, *qkwh, *vwh, *pwh;
    float* pos_buf;
    cudaGetSymbolAddress((void**)&xh, gx_h);
    cudaGetSymbolAddress((void**)&qkh, gqk_h);
    cudaGetSymbolAddress((void**)&vh, gv_h);
    cudaGetSymbolAddress((void**)&oh, go_h);
    cudaGetSymbolAddress((void**)&qkwh, gqkw_h);
    cudaGetSymbolAddress((void**)&vwh, gvw_h);
    cudaGetSymbolAddress((void**)&pwh, gpw_h);
    cudaGetSymbolAddress((void**)&pos_buf, g_pos);

    cudaFuncSetAttribute(gemm_h<false>, cudaFuncAttributeMaxDynamicSharedMemorySize, HSM_BYTES);
    cudaFuncSetAttribute(gemm_h<true>, cudaFuncAttributeMaxDynamicSharedMemorySize, HSM_BYTES);

    // converts
    {
        int n = MTOT * DIM;
        conv_h<<<n / 1024, 256>>>(x, xh, n);
        conv_h<<<(2 * DIM * DIM) / 1024, 256>>>(qk_w, qkwh, 2 * DIM * DIM);
        conv_h<<<(DIM * DIM) / 1024, 256>>>(v_w, vwh, DIM * DIM);
        conv_h<<<(DIM * DIM) / 1024, 256>>>(proj_w, pwh, DIM * DIM);
    }
    pos_kernel<<<729, 384>>>(w1_w, w1_b, w2, b2, pos_buf);

    // qk projection
    {
        dim3 grid(2 * DIM / 128, MTOT / 128);
        gemm_h<false><<<grid, 256, HSM_BYTES>>>(xh, qkwh, nullptr, qkh, MTOT, 2 * DIM, DIM);
    }
    // v projection
    {
        dim3 grid(DIM / 128, MTOT / 128);
        gemm_h<false><<<grid, 256, HSM_BYTES>>>(xh, vwh, nullptr, vh, MTOT, DIM, DIM);
    }
    // fused attention
    {
        int smem_bytes = ATTN_SM_WORDS * 4;
        cudaFuncSetAttribute(attn_mma, cudaFuncAttributeMaxDynamicSharedMemorySize, smem_bytes);
        attn_mma<<<BATCH * HEADS, 256, smem_bytes>>>(qkh, vh, pos_buf, oh);
    }
    // output projection (float out, with bias)
    {
        dim3 grid(DIM / 128, MTOT / 128);
        gemm_h<true><<<grid, 256, HSM_BYTES>>>(oh, pwh, proj_b, out, MTOT, DIM, DIM);
    }
}

// round 12
// speedup vs baseline: 7.9067x; 1.1084x over previous
#include <cuda_runtime.h>
#include <cuda_fp16.h>
#include <math.h>
#include <stdint.h>

#define DIM 768
#define HEADS 12
#define HEAD_DIM 64
#define BATCH 64
#define SEQ 196
#define MTOT (BATCH * SEQ)      // 12544
#define SCALE 0.125f
#define QKVS 2304               // combined q|k|v row stride

// ---------------- scratch (all fp16 intermediates) ----------------
__device__ __half gx_h[(size_t)MTOT * DIM];
__device__ __half gqkv_h[(size_t)MTOT * QKVS];     // q|k|v
__device__ __half go_h[(size_t)MTOT * DIM];
__device__ __half gqkvw_h[QKVS * DIM];             // qk_w rows 0..1535, v_w rows 1536..2303
__device__ __half gpw_h[DIM * DIM];
__device__ float g_pos[HEADS * 729];

// ---------------- helpers ----------------
__device__ __forceinline__ uint32_t packh2(float x, float y) {
    __half2 h = __floats2half2_rn(x, y);
    return *(uint32_t*)&h;
}

__device__ __forceinline__ void mma_f16(float* c, const uint32_t* a, uint32_t b0, uint32_t b1) {
    asm volatile(
        "mma.sync.aligned.m16n8k16.row.col.f32.f16.f16.f32 "
        "{%0,%1,%2,%3}, {%4,%5,%6,%7}, {%8,%9}, {%0,%1,%2,%3};\n"
        : "+f"(c[0]), "+f"(c[1]), "+f"(c[2]), "+f"(c[3])
        : "r"(a[0]), "r"(a[1]), "r"(a[2]), "r"(a[3]), "r"(b0), "r"(b1));
}

__device__ __forceinline__ uint32_t smem_u32(const void* p) {
    uint32_t a;
    asm("{ .reg .u64 t; cvta.to.shared.u64 t, %1; cvt.u32.u64 %0, t; }" : "=r"(a) : "l"(p));
    return a;
}

#define LDSM_X4(r0, r1, r2, r3, addr) \
    asm volatile("ldmatrix.sync.aligned.m8n8.x4.shared.b16 {%0,%1,%2,%3}, [%4];" \
                 : "=r"(r0), "=r"(r1), "=r"(r2), "=r"(r3) : "r"(addr))

#define CP_ASYNC16(smaddr, gptr) \
    asm volatile("cp.async.cg.shared.global [%0], [%1], 16;" :: "r"(smaddr), "l"(gptr) : "memory")
#define CP_COMMIT() asm volatile("cp.async.commit_group;" ::: "memory")
#define CP_WAIT(n)  asm volatile("cp.async.wait_group %0;" :: "n"(n) : "memory")

// ---------------- fp32 -> fp16 convert ----------------
__global__ void conv_h(const float* __restrict__ src, __half* __restrict__ dst, int n) {
    int i = (blockIdx.x * 256 + threadIdx.x) * 4;
    if (i < n) {
        float4 v = *(const float4*)&src[i];
        uint2 p;
        p.x = packh2(v.x, v.y);
        p.y = packh2(v.z, v.w);
        *(uint2*)&dst[i] = p;
    }
}

// ---------------- pos table ----------------
__global__ void pos_kernel(const float* __restrict__ w1,
                           const float* __restrict__ b1,
                           const float* __restrict__ w2,
                           const float* __restrict__ b2,
                           float* __restrict__ out)
{
    int c = blockIdx.x;
    float dx = (float)(c % 27 - 13);
    float dy = (float)(c / 27 - 13);
    int h = threadIdx.x >> 5;
    int lane = threadIdx.x & 31;
    float sum = 0.f;
#pragma unroll
    for (int mm = lane; mm < HEAD_DIM; mm += 32) {
        int g = h * HEAD_DIM + mm;
        float t = fmaf(dx, w1[g * 2 + 0], fmaf(dy, w1[g * 2 + 1], b1[g]));
        t = fmaxf(t, 0.f);
        sum += t * w2[g];
    }
#pragma unroll
    for (int o = 16; o > 0; o >>= 1) sum += __shfl_xor_sync(0xffffffffu, sum, o);
    if (lane == 0) out[h * 729 + c] = sum + b2[h];
}

// ---------------- pure-fp16 GEMM, cp.async double-buffered, BK=64, LDSM frags ----
#define HSTRW 36
#define HBUF_W (2 * 128 * HSTRW)    // words per buffer (A then B)
#define HSM_BYTES (2 * HBUF_W * 4)  // 73728

template <bool OUT_FLOAT>
__global__ __launch_bounds__(256, 2)
void gemm_h(const __half* __restrict__ A, const __half* __restrict__ B,
            const float* __restrict__ bias, void* __restrict__ Cout,
            int M, int N, int K)
{
    extern __shared__ uint32_t sm[];

    int tid = threadIdx.x;
    int lane = tid & 31;
    int w = tid >> 5;
    int wm = w >> 2;            // 0..1
    int wn = w & 3;             // 0..3
    int lq = lane >> 2;         // 0..7
    int lr = lane & 3;          // 0..3
    int m0 = blockIdx.y * 128;
    int n0 = blockIdx.x * 128;

    // ldmatrix lane-address selectors
    uint32_t rowSelA = (lane & 7) + ((lane >> 3) & 1) * 8;  // m1,m3 rows +8
    uint32_t colSelA = (lane >> 4) * 4;                     // m2,m3 k +8
    uint32_t rowSelB = (lane & 7) + (lane >> 4) * 8;        // m2,m3 next n-tile
    uint32_t colSelB = ((lane >> 3) & 1) * 4;               // m1,m3 k +8

    float acc[4][4][4];
#pragma unroll
    for (int i = 0; i < 4; i++)
#pragma unroll
        for (int j = 0; j < 4; j++)
#pragma unroll
            for (int t = 0; t < 4; t++) acc[i][j][t] = 0.f;

    uint32_t smb = smem_u32(sm);
    int NT_K = K / 64;

    auto issue = [&](int buf, int k0) {
#pragma unroll
        for (int i = 0; i < 4; i++) {
            int c = tid + i * 256;
            int row = c >> 3, c8 = c & 7;
            uint32_t dstA = smb + (buf * HBUF_W + row * HSTRW + c8 * 4) * 4;
            CP_ASYNC16(dstA, A + (size_t)(m0 + row) * K + k0 + c8 * 8);
            uint32_t dstB = smb + (buf * HBUF_W + (128 + row) * HSTRW + c8 * 4) * 4;
            CP_ASYNC16(dstB, B + (size_t)(n0 + row) * K + k0 + c8 * 8);
        }
        CP_COMMIT();
    };

    issue(0, 0);

    for (int kt = 0; kt < NT_K; kt++) {
        if (kt + 1 < NT_K) {
            issue((kt + 1) & 1, (kt + 1) * 64);
            CP_WAIT(1);
        } else {
            CP_WAIT(0);
        }
        __syncthreads();

        uint32_t abase = smb + ((kt & 1) * HBUF_W) * 4;
        uint32_t aAddr = abase + ((wm * 64 + rowSelA) * HSTRW + colSelA) * 4;
        uint32_t bAddr = abase + ((128 + wn * 32 + rowSelB) * HSTRW + colSelB) * 4;

#pragma unroll
        for (int ks = 0; ks < 4; ks++) {
            int kb = ks * 8;
            uint32_t af[4][4], bf[4][2];
#pragma unroll
            for (int i = 0; i < 4; i++)
                LDSM_X4(af[i][0], af[i][1], af[i][2], af[i][3],
                        aAddr + (i * 16 * HSTRW + kb) * 4);
#pragma unroll
            for (int jp = 0; jp < 2; jp++)
                LDSM_X4(bf[2 * jp][0], bf[2 * jp][1], bf[2 * jp + 1][0], bf[2 * jp + 1][1],
                        bAddr + (jp * 16 * HSTRW + kb) * 4);
#pragma unroll
            for (int i = 0; i < 4; i++)
#pragma unroll
                for (int j = 0; j < 4; j++)
                    mma_f16(acc[i][j], af[i], bf[j][0], bf[j][1]);
        }
        __syncthreads();
    }

#pragma unroll
    for (int i = 0; i < 4; i++) {
#pragma unroll
        for (int j = 0; j < 4; j++) {
            int row = m0 + wm * 64 + i * 16 + lq;
            int col = n0 + wn * 32 + j * 8 + lr * 2;
            float b0 = bias ? bias[col] : 0.f;
            float b1 = bias ? bias[col + 1] : 0.f;
            if (OUT_FLOAT) {
                float* C = (float*)Cout;
                *(float2*)&C[(size_t)row * N + col] =
                    make_float2(acc[i][j][0] + b0, acc[i][j][1] + b1);
                *(float2*)&C[(size_t)(row + 8) * N + col] =
                    make_float2(acc[i][j][2] + b0, acc[i][j][3] + b1);
            } else {
                __half* C = (__half*)Cout;
                *(uint32_t*)&C[(size_t)row * N + col] = packh2(acc[i][j][0] + b0, acc[i][j][1] + b1);
                *(uint32_t*)&C[(size_t)(row + 8) * N + col] = packh2(acc[i][j][2] + b0, acc[i][j][3] + b1);
            }
        }
    }
}

// ---------------- FP16 MMA attention (qkv combined input), LDSM frags ----------
#define KSH_W 36            // words per K row (72 halves)
#define VTS_W 116           // words per Vt row (232 halves)
#define NPAD 224
#define CNT 14
#define ATTN_SM_WORDS (NPAD * KSH_W + 64 * VTS_W + 729 + NPAD)

__global__ __launch_bounds__(256, 2)
void attn_mma(const __half* __restrict__ qkv,
              const float* __restrict__ pos,
              __half* __restrict__ og)
{
    extern __shared__ uint32_t smu[];
    uint32_t* Kw   = smu;                        // [224][36] words
    uint32_t* Vw   = Kw + NPAD * KSH_W;          // [64][116] words
    float*    posh = (float*)(Vw + 64 * VTS_W);  // 729
    int*      colc = (int*)(posh + 729);         // 224

    int bh = blockIdx.x;
    int b = bh / HEADS;
    int h = bh % HEADS;
    int tid = threadIdx.x;
    int w = tid >> 5;
    int lane = tid & 31;
    int lq = lane >> 2;
    int lr = lane & 3;

    uint32_t rowSelB = (lane & 7) + (lane >> 4) * 8;
    uint32_t colSelB = ((lane >> 3) & 1) * 4;
    uint32_t kAddrBase, vAddrBase;
    {
        uint32_t kb = smem_u32(Kw), vb = smem_u32(Vw);
        kAddrBase = kb + (rowSelB * KSH_W + colSelB) * 4;
        vAddrBase = vb + (rowSelB * VTS_W + colSelB) * 4;
    }

    // zero pads: K rows 196..223, Vt col words 98..115
    for (int idx = tid; idx < 28 * KSH_W; idx += 256)
        Kw[196 * KSH_W + idx] = 0;
    for (int idx = tid; idx < 64 * 18; idx += 256) {
        int d = idx / 18, wz = 98 + idx % 18;
        Vw[d * VTS_W + wz] = 0;
    }

    // stage K rows 0..195 (uint4 copies)
    for (int idx = tid; idx < SEQ * 8; idx += 256) {
        int j = idx >> 3, c8 = idx & 7;
        *(uint4*)&Kw[j * KSH_W + c8 * 4] =
            *(const uint4*)&qkv[(size_t)(b * SEQ + j) * QKVS + DIM + h * HEAD_DIM + c8 * 8];
    }
    // stage V transposed
    {
        __half* Vh = (__half*)Vw;
        for (int idx = tid; idx < SEQ * 8; idx += 256) {
            int j = idx >> 3, d8 = (idx & 7) * 8;
            uint4 val = *(const uint4*)&qkv[(size_t)(b * SEQ + j) * QKVS + 2 * DIM + h * HEAD_DIM + d8];
            const __half* hv = (const __half*)&val;
#pragma unroll
            for (int t = 0; t < 8; t++)
                Vh[(d8 + t) * (VTS_W * 2) + j] = hv[t];
        }
    }
    for (int c = tid; c < 729; c += 256) posh[c] = pos[h * 729 + c];
    for (int c = tid; c < NPAD; c += 256) {
        int cc = c > 195 ? 195 : c;
        colc[c] = (cc / 14) * 27 + (cc % 14);
    }
    __syncthreads();

    for (int mt = w; mt < 13; mt += 8) {
        int m0 = mt * 16;
        int r1 = m0 + lq, r2 = r1 + 8;
        int r1c = r1 > 195 ? 195 : r1;
        int r2c = r2 > 195 ? 195 : r2;
        const __half* q1 = &qkv[(size_t)(b * SEQ + r1c) * QKVS + h * HEAD_DIM];
        const __half* q2 = &qkv[(size_t)(b * SEQ + r2c) * QKVS + h * HEAD_DIM];

        uint32_t af[4][4];
#pragma unroll
        for (int ks = 0; ks < 4; ks++) {
            af[ks][0] = *(const uint32_t*)&q1[16 * ks + 2 * lr];
            af[ks][1] = *(const uint32_t*)&q2[16 * ks + 2 * lr];
            af[ks][2] = *(const uint32_t*)&q1[16 * ks + 8 + 2 * lr];
            af[ks][3] = *(const uint32_t*)&q2[16 * ks + 8 + 2 * lr];
        }

        int base1 = (13 - r1c / 14) * 27 + (13 - r1c % 14);
        int base2 = (13 - r2c / 14) * 27 + (13 - r2c % 14);

        float ao[8][4];
#pragma unroll
        for (int nt = 0; nt < 8; nt++)
#pragma unroll
            for (int t = 0; t < 4; t++) ao[nt][t] = 0.f;
        float sum1 = 0.f, sum2 = 0.f;

#pragma unroll
        for (int ch = 0; ch < 2; ch++) {
            float acc[CNT][4];
#pragma unroll
            for (int nt = 0; nt < CNT; nt++)
#pragma unroll
                for (int t = 0; t < 4; t++) acc[nt][t] = 0.f;

#pragma unroll
            for (int ks = 0; ks < 4; ks++) {
#pragma unroll
                for (int np = 0; np < 7; np++) {
                    uint32_t bf[2][2];
                    LDSM_X4(bf[0][0], bf[0][1], bf[1][0], bf[1][1],
                            kAddrBase + ((ch * CNT + 2 * np) * 8 * KSH_W + 8 * ks) * 4);
                    mma_f16(acc[2 * np], af[ks], bf[0][0], bf[0][1]);
                    mma_f16(acc[2 * np + 1], af[ks], bf[1][0], bf[1][1]);
                }
            }

#pragma unroll
            for (int nt = 0; nt < CNT; nt++) {
#pragma unroll
                for (int t = 0; t < 2; t++) {
                    int c = ch * 112 + nt * 8 + lr * 2 + t;
                    int code = colc[c];
                    float p1 = posh[code + base1];
                    float p2 = posh[code + base2];
                    float e1 = __expf(acc[nt][t] * SCALE * p1);
                    float e2 = __expf(acc[nt][2 + t] * SCALE * p2);
                    if (c > 195) { e1 = 0.f; e2 = 0.f; }
                    acc[nt][t] = e1;
                    acc[nt][2 + t] = e2;
                    sum1 += e1;
                    sum2 += e2;
                }
            }

#pragma unroll
            for (int ks = 0; ks < 7; ks++) {
                uint32_t pa[4];
                pa[0] = packh2(acc[2 * ks][0], acc[2 * ks][1]);
                pa[1] = packh2(acc[2 * ks][2], acc[2 * ks][3]);
                pa[2] = packh2(acc[2 * ks + 1][0], acc[2 * ks + 1][1]);
                pa[3] = packh2(acc[2 * ks + 1][2], acc[2 * ks + 1][3]);
#pragma unroll
                for (int np = 0; np < 4; np++) {
                    uint32_t bf[2][2];
                    LDSM_X4(bf[0][0], bf[0][1], bf[1][0], bf[1][1],
                            vAddrBase + (np * 16 * VTS_W + 8 * (ch * 7 + ks)) * 4);
                    mma_f16(ao[2 * np], pa, bf[0][0], bf[0][1]);
                    mma_f16(ao[2 * np + 1], pa, bf[1][0], bf[1][1]);
                }
            }
        }

        sum1 += __shfl_xor_sync(0xffffffffu, sum1, 1);
        sum1 += __shfl_xor_sync(0xffffffffu, sum1, 2);
        sum2 += __shfl_xor_sync(0xffffffffu, sum2, 1);
        sum2 += __shfl_xor_sync(0xffffffffu, sum2, 2);
        float inv1 = 1.f / sum1;
        float inv2 = 1.f / sum2;

#pragma unroll
        for (int nt = 0; nt < 8; nt++) {
            int c = nt * 8 + lr * 2;
            if (r1 < SEQ)
                *(uint32_t*)&og[(size_t)(b * SEQ + r1) * DIM + h * HEAD_DIM + c] =
                    packh2(ao[nt][0] * inv1, ao[nt][1] * inv1);
            if (r2 < SEQ)
                *(uint32_t*)&og[(size_t)(b * SEQ + r2) * DIM + h * HEAD_DIM + c] =
                    packh2(ao[nt][2] * inv2, ao[nt][3] * inv2);
        }
    }
}

// ---------------- launch ----------------
extern "C" void kernel_launch(void* const* d_in, const int* in_sizes, int n_in,
                              void* d_out, int out_size)
{
    const float* x      = (const float*)d_in[0];
    const float* qk_w   = (const float*)d_in[1];
    const float* v_w    = (const float*)d_in[2];
    const float* w1_w   = (const float*)d_in[3];
    const float* w1_b   = (const float*)d_in[4];
    const float* w2     = (const float*)d_in[5];
    const float* b2     = (const float*)d_in[6];
    const float* proj_w = (const float*)d_in[7];
    const float* proj_b = (const float*)d_in[8];
    float* out = (float*)d_out;

    __half *xh, *qkvh, *oh, *qkvwh, *pwh;
    float* pos_buf;
    cudaGetSymbolAddress((void**)&xh, gx_h);
    cudaGetSymbolAddress((void**)&qkvh, gqkv_h);
    cudaGetSymbolAddress((void**)&oh, go_h);
    cudaGetSymbolAddress((void**)&qkvwh, gqkvw_h);
    cudaGetSymbolAddress((void**)&pwh, gpw_h);
    cudaGetSymbolAddress((void**)&pos_buf, g_pos);

    cudaFuncSetAttribute(gemm_h<false>, cudaFuncAttributeMaxDynamicSharedMemorySize, HSM_BYTES);
    cudaFuncSetAttribute(gemm_h<true>, cudaFuncAttributeMaxDynamicSharedMemorySize, HSM_BYTES);

    // converts (qk_w and v_w pack into one combined weight buffer)
    {
        int n = MTOT * DIM;
        conv_h<<<n / 1024, 256>>>(x, xh, n);
        conv_h<<<(2 * DIM * DIM) / 1024, 256>>>(qk_w, qkvwh, 2 * DIM * DIM);
        conv_h<<<(DIM * DIM) / 1024, 256>>>(v_w, qkvwh + (size_t)2 * DIM * DIM, DIM * DIM);
        conv_h<<<(DIM * DIM) / 1024, 256>>>(proj_w, pwh, DIM * DIM);
    }
    pos_kernel<<<729, 384>>>(w1_w, w1_b, w2, b2, pos_buf);

    // fused qkv projection: (12544, 2304)
    {
        dim3 grid(QKVS / 128, MTOT / 128);
        gemm_h<false><<<grid, 256, HSM_BYTES>>>(xh, qkvwh, nullptr, qkvh, MTOT, QKVS, DIM);
    }
    // fused attention
    {
        int smem_bytes = ATTN_SM_WORDS * 4;
        cudaFuncSetAttribute(attn_mma, cudaFuncAttributeMaxDynamicSharedMemorySize, smem_bytes);
        attn_mma<<<BATCH * HEADS, 256, smem_bytes>>>(qkvh, pos_buf, oh);
    }
    // output projection (float out, with bias)
    {
        dim3 grid(DIM / 128, MTOT / 128);
        gemm_h<true><<<grid, 256, HSM_BYTES>>>(oh, pwh, proj_b, out, MTOT, DIM, DIM);
    }
}

// round 14
// speedup vs baseline: 8.3583x; 1.0571x over previous
#include <cuda_runtime.h>
#include <cuda_fp16.h>
#include <math.h>
#include <stdint.h>

#define DIM 768
#define HEADS 12
#define HEAD_DIM 64
#define BATCH 64
#define SEQ 196
#define MTOT (BATCH * SEQ)      // 12544
#define SCALE 0.125f
#define QKVS 2304               // combined q|k|v row stride

// ---------------- scratch (all fp16 intermediates) ----------------
__device__ __half gx_h[(size_t)MTOT * DIM];
__device__ __half gqkv_h[(size_t)MTOT * QKVS];     // q|k|v
__device__ __half go_h[(size_t)MTOT * DIM];
__device__ __half gqkvw_h[QKVS * DIM];             // qk_w rows 0..1535, v_w rows 1536..2303
__device__ __half gpw_h[DIM * DIM];
__device__ float g_pos[HEADS * 729];

// ---------------- helpers ----------------
__device__ __forceinline__ uint32_t packh2(float x, float y) {
    __half2 h = __floats2half2_rn(x, y);
    return *(uint32_t*)&h;
}

__device__ __forceinline__ void mma_f16(float* c, const uint32_t* a, uint32_t b0, uint32_t b1) {
    asm volatile(
        "mma.sync.aligned.m16n8k16.row.col.f32.f16.f16.f32 "
        "{%0,%1,%2,%3}, {%4,%5,%6,%7}, {%8,%9}, {%0,%1,%2,%3};\n"
        : "+f"(c[0]), "+f"(c[1]), "+f"(c[2]), "+f"(c[3])
        : "r"(a[0]), "r"(a[1]), "r"(a[2]), "r"(a[3]), "r"(b0), "r"(b1));
}

__device__ __forceinline__ uint32_t smem_u32(const void* p) {
    uint32_t a;
    asm("{ .reg .u64 t; cvta.to.shared.u64 t, %1; cvt.u32.u64 %0, t; }" : "=r"(a) : "l"(p));
    return a;
}

#define LDSM_X4(r0, r1, r2, r3, addr) \
    asm volatile("ldmatrix.sync.aligned.m8n8.x4.shared.b16 {%0,%1,%2,%3}, [%4];" \
                 : "=r"(r0), "=r"(r1), "=r"(r2), "=r"(r3) : "r"(addr))

#define LDSM_X4_T(r0, r1, r2, r3, addr) \
    asm volatile("ldmatrix.sync.aligned.m8n8.x4.trans.shared.b16 {%0,%1,%2,%3}, [%4];" \
                 : "=r"(r0), "=r"(r1), "=r"(r2), "=r"(r3) : "r"(addr))

#define CP_ASYNC16(smaddr, gptr) \
    asm volatile("cp.async.cg.shared.global [%0], [%1], 16;" :: "r"(smaddr), "l"(gptr) : "memory")
#define CP_COMMIT() asm volatile("cp.async.commit_group;" ::: "memory")
#define CP_WAIT(n)  asm volatile("cp.async.wait_group %0;" :: "n"(n) : "memory")

// ---------------- merged fp32 -> fp16 convert (x, qk_w, v_w, proj_w) ----------------
#define NX (MTOT * DIM)
#define NQK (2 * DIM * DIM)
#define NV (DIM * DIM)
#define NCONV_TOT (NX + NQK + NV + NV)

__global__ void conv_all(const float* __restrict__ x, const float* __restrict__ qk_w,
                         const float* __restrict__ v_w, const float* __restrict__ proj_w,
                         __half* __restrict__ xh, __half* __restrict__ qkvwh,
                         __half* __restrict__ pwh)
{
    size_t i = ((size_t)blockIdx.x * 256 + threadIdx.x) * 4;
    if (i >= NCONV_TOT) return;
    const float* src;
    __half* dst;
    size_t off;
    if (i < NX) { src = x; dst = xh; off = i; }
    else if (i < NX + NQK) { src = qk_w; dst = qkvwh; off = i - NX; }
    else if (i < NX + NQK + NV) { src = v_w; dst = qkvwh + NQK; off = i - NX - NQK; }
    else { src = proj_w; dst = pwh; off = i - NX - NQK - NV; }
    float4 v = *(const float4*)&src[off];
    uint2 p;
    p.x = packh2(v.x, v.y);
    p.y = packh2(v.z, v.w);
    *(uint2*)&dst[off] = p;
}

// ---------------- pos table ----------------
__global__ void pos_kernel(const float* __restrict__ w1,
                           const float* __restrict__ b1,
                           const float* __restrict__ w2,
                           const float* __restrict__ b2,
                           float* __restrict__ out)
{
    int c = blockIdx.x;
    float dx = (float)(c % 27 - 13);
    float dy = (float)(c / 27 - 13);
    int h = threadIdx.x >> 5;
    int lane = threadIdx.x & 31;
    float sum = 0.f;
#pragma unroll
    for (int mm = lane; mm < HEAD_DIM; mm += 32) {
        int g = h * HEAD_DIM + mm;
        float t = fmaf(dx, w1[g * 2 + 0], fmaf(dy, w1[g * 2 + 1], b1[g]));
        t = fmaxf(t, 0.f);
        sum += t * w2[g];
    }
#pragma unroll
    for (int o = 16; o > 0; o >>= 1) sum += __shfl_xor_sync(0xffffffffu, sum, o);
    if (lane == 0) out[h * 729 + c] = sum + b2[h];
}

// ---------------- pure-fp16 GEMM: 3-stage cp.async pipeline, 1 sync/tile ----------
#define HSTRW 36
#define HBUF_W (2 * 128 * HSTRW)        // words per stage (A then B)
#define HSM_BYTES (3 * HBUF_W * 4)      // 110592

template <bool OUT_FLOAT>
__global__ __launch_bounds__(256, 2)
void gemm_h(const __half* __restrict__ A, const __half* __restrict__ B,
            const float* __restrict__ bias, void* __restrict__ Cout,
            int M, int N, int K)
{
    extern __shared__ uint32_t sm[];

    int tid = threadIdx.x;
    int lane = tid & 31;
    int w = tid >> 5;
    int wm = w >> 2;            // 0..1
    int wn = w & 3;             // 0..3
    int lq = lane >> 2;         // 0..7
    int lr = lane & 3;          // 0..3
    int m0 = blockIdx.y * 128;
    int n0 = blockIdx.x * 128;

    uint32_t rowSelA = (lane & 7) + ((lane >> 3) & 1) * 8;
    uint32_t colSelA = (lane >> 4) * 4;
    uint32_t rowSelB = (lane & 7) + (lane >> 4) * 8;
    uint32_t colSelB = ((lane >> 3) & 1) * 4;

    float acc[4][4][4];
#pragma unroll
    for (int i = 0; i < 4; i++)
#pragma unroll
        for (int j = 0; j < 4; j++)
#pragma unroll
            for (int t = 0; t < 4; t++) acc[i][j][t] = 0.f;

    uint32_t smb = smem_u32(sm);
    int NT_K = K / 64;

    auto issue = [&](int buf, int k0) {
#pragma unroll
        for (int i = 0; i < 4; i++) {
            int c = tid + i * 256;
            int row = c >> 3, c8 = c & 7;
            uint32_t dstA = smb + (buf * HBUF_W + row * HSTRW + c8 * 4) * 4;
            CP_ASYNC16(dstA, A + (size_t)(m0 + row) * K + k0 + c8 * 8);
            uint32_t dstB = smb + (buf * HBUF_W + (128 + row) * HSTRW + c8 * 4) * 4;
            CP_ASYNC16(dstB, B + (size_t)(n0 + row) * K + k0 + c8 * 8);
        }
        CP_COMMIT();
    };

    issue(0, 0);
    issue(1, 64);

    int buf = 0;
    for (int kt = 0; kt < NT_K; kt++) {
        CP_WAIT(1);                 // stage kt landed (kt+1 may still fly)
        __syncthreads();            // all warps done with the buffer we're about to refill

        if (kt + 2 < NT_K) issue((kt + 2) % 3, (kt + 2) * 64);

        uint32_t abase = smb + (buf * HBUF_W) * 4;
        uint32_t aAddr = abase + ((wm * 64 + rowSelA) * HSTRW + colSelA) * 4;
        uint32_t bAddr = abase + ((128 + wn * 32 + rowSelB) * HSTRW + colSelB) * 4;

#pragma unroll
        for (int ks = 0; ks < 4; ks++) {
            int kb = ks * 8;
            uint32_t af[4][4], bf[4][2];
#pragma unroll
            for (int i = 0; i < 4; i++)
                LDSM_X4(af[i][0], af[i][1], af[i][2], af[i][3],
                        aAddr + (i * 16 * HSTRW + kb) * 4);
#pragma unroll
            for (int jp = 0; jp < 2; jp++)
                LDSM_X4(bf[2 * jp][0], bf[2 * jp][1], bf[2 * jp + 1][0], bf[2 * jp + 1][1],
                        bAddr + (jp * 16 * HSTRW + kb) * 4);
#pragma unroll
            for (int i = 0; i < 4; i++)
#pragma unroll
                for (int j = 0; j < 4; j++)
                    mma_f16(acc[i][j], af[i], bf[j][0], bf[j][1]);
        }
        buf = (buf + 1) % 3;
    }

#pragma unroll
    for (int i = 0; i < 4; i++) {
#pragma unroll
        for (int j = 0; j < 4; j++) {
            int row = m0 + wm * 64 + i * 16 + lq;
            int col = n0 + wn * 32 + j * 8 + lr * 2;
            float b0 = bias ? bias[col] : 0.f;
            float b1 = bias ? bias[col + 1] : 0.f;
            if (OUT_FLOAT) {
                float* C = (float*)Cout;
                *(float2*)&C[(size_t)row * N + col] =
                    make_float2(acc[i][j][0] + b0, acc[i][j][1] + b1);
                *(float2*)&C[(size_t)(row + 8) * N + col] =
                    make_float2(acc[i][j][2] + b0, acc[i][j][3] + b1);
            } else {
                __half* C = (__half*)Cout;
                *(uint32_t*)&C[(size_t)row * N + col] = packh2(acc[i][j][0] + b0, acc[i][j][1] + b1);
                *(uint32_t*)&C[(size_t)(row + 8) * N + col] = packh2(acc[i][j][2] + b0, acc[i][j][3] + b1);
            }
        }
    }
}

// ---------------- FP16 MMA attention: V untransposed + ldmatrix.trans ----------
// smem: K [224][72 halves], V [224][72 halves] (rows j, cols d), pos[729], colc[224]
#define KSH_W 36            // words per K row
#define VSH_W 36            // words per V row
#define NPAD 224
#define CNT 14
#define ATTN_SM_WORDS (NPAD * KSH_W + NPAD * VSH_W + 729 + NPAD)

__global__ __launch_bounds__(256, 2)
void attn_mma(const __half* __restrict__ qkv,
              const float* __restrict__ pos,
              __half* __restrict__ og)
{
    extern __shared__ uint32_t smu[];
    uint32_t* Kw   = smu;                        // [224][36] words
    uint32_t* Vw   = Kw + NPAD * KSH_W;          // [224][36] words (V rows j)
    float*    posh = (float*)(Vw + NPAD * VSH_W);
    int*      colc = (int*)(posh + 729);

    int bh = blockIdx.x;
    int b = bh / HEADS;
    int h = bh % HEADS;
    int tid = threadIdx.x;
    int w = tid >> 5;
    int lane = tid & 31;
    int lq = lane >> 2;
    int lr = lane & 3;

    // K (non-trans) selectors
    uint32_t rowSelB = (lane & 7) + (lane >> 4) * 8;
    uint32_t colSelB = ((lane >> 3) & 1) * 4;
    // V (trans) selectors: rows = j (m dim of stored V), cols = d
    uint32_t rowSelV = (lane & 7) + ((lane >> 3) & 1) * 8;  // j offset
    uint32_t colSelV = (lane >> 4) * 8;                     // d offset (halves)
    uint32_t kAddrBase, vAddrBase;
    {
        uint32_t kb = smem_u32(Kw), vb = smem_u32(Vw);
        kAddrBase = kb + (rowSelB * KSH_W + colSelB) * 4;
        vAddrBase = vb + rowSelV * VSH_W * 4 + colSelV * 2;
    }

    // zero pads: K and V rows 196..223
    for (int idx = tid; idx < 28 * KSH_W; idx += 256) {
        Kw[196 * KSH_W + idx] = 0;
        Vw[196 * VSH_W + idx] = 0;
    }

    // stage K and V rows 0..195 (pure uint4 copies)
    for (int idx = tid; idx < SEQ * 8; idx += 256) {
        int j = idx >> 3, c8 = idx & 7;
        *(uint4*)&Kw[j * KSH_W + c8 * 4] =
            *(const uint4*)&qkv[(size_t)(b * SEQ + j) * QKVS + DIM + h * HEAD_DIM + c8 * 8];
        *(uint4*)&Vw[j * VSH_W + c8 * 4] =
            *(const uint4*)&qkv[(size_t)(b * SEQ + j) * QKVS + 2 * DIM + h * HEAD_DIM + c8 * 8];
    }
    for (int c = tid; c < 729; c += 256) posh[c] = pos[h * 729 + c];
    for (int c = tid; c < NPAD; c += 256) {
        int cc = c > 195 ? 195 : c;
        colc[c] = (cc / 14) * 27 + (cc % 14);
    }
    __syncthreads();

    for (int mt = w; mt < 13; mt += 8) {
        int m0 = mt * 16;
        int r1 = m0 + lq, r2 = r1 + 8;
        int r1c = r1 > 195 ? 195 : r1;
        int r2c = r2 > 195 ? 195 : r2;
        const __half* q1 = &qkv[(size_t)(b * SEQ + r1c) * QKVS + h * HEAD_DIM];
        const __half* q2 = &qkv[(size_t)(b * SEQ + r2c) * QKVS + h * HEAD_DIM];

        uint32_t af[4][4];
#pragma unroll
        for (int ks = 0; ks < 4; ks++) {
            af[ks][0] = *(const uint32_t*)&q1[16 * ks + 2 * lr];
            af[ks][1] = *(const uint32_t*)&q2[16 * ks + 2 * lr];
            af[ks][2] = *(const uint32_t*)&q1[16 * ks + 8 + 2 * lr];
            af[ks][3] = *(const uint32_t*)&q2[16 * ks + 8 + 2 * lr];
        }

        int base1 = (13 - r1c / 14) * 27 + (13 - r1c % 14);
        int base2 = (13 - r2c / 14) * 27 + (13 - r2c % 14);

        float ao[8][4];
#pragma unroll
        for (int nt = 0; nt < 8; nt++)
#pragma unroll
            for (int t = 0; t < 4; t++) ao[nt][t] = 0.f;
        float sum1 = 0.f, sum2 = 0.f;

#pragma unroll
        for (int ch = 0; ch < 2; ch++) {
            float acc[CNT][4];
#pragma unroll
            for (int nt = 0; nt < CNT; nt++)
#pragma unroll
                for (int t = 0; t < 4; t++) acc[nt][t] = 0.f;

#pragma unroll
            for (int ks = 0; ks < 4; ks++) {
#pragma unroll
                for (int np = 0; np < 7; np++) {
                    uint32_t bf[2][2];
                    LDSM_X4(bf[0][0], bf[0][1], bf[1][0], bf[1][1],
                            kAddrBase + ((ch * CNT + 2 * np) * 8 * KSH_W + 8 * ks) * 4);
                    mma_f16(acc[2 * np], af[ks], bf[0][0], bf[0][1]);
                    mma_f16(acc[2 * np + 1], af[ks], bf[1][0], bf[1][1]);
                }
            }

#pragma unroll
            for (int nt = 0; nt < CNT; nt++) {
#pragma unroll
                for (int t = 0; t < 2; t++) {
                    int c = ch * 112 + nt * 8 + lr * 2 + t;
                    int code = colc[c];
                    float p1 = posh[code + base1];
                    float p2 = posh[code + base2];
                    float e1 = __expf(acc[nt][t] * SCALE * p1);
                    float e2 = __expf(acc[nt][2 + t] * SCALE * p2);
                    if (c > 195) { e1 = 0.f; e2 = 0.f; }
                    acc[nt][t] = e1;
                    acc[nt][2 + t] = e2;
                    sum1 += e1;
                    sum2 += e2;
                }
            }

            // PV: B-fragments via ldmatrix.trans on untransposed V
#pragma unroll
            for (int ks = 0; ks < 7; ks++) {
                int j0 = 16 * (ch * 7 + ks);
                uint32_t pa[4];
                pa[0] = packh2(acc[2 * ks][0], acc[2 * ks][1]);
                pa[1] = packh2(acc[2 * ks][2], acc[2 * ks][3]);
                pa[2] = packh2(acc[2 * ks + 1][0], acc[2 * ks + 1][1]);
                pa[3] = packh2(acc[2 * ks + 1][2], acc[2 * ks + 1][3]);
#pragma unroll
                for (int np = 0; np < 4; np++) {
                    uint32_t bf[2][2];
                    LDSM_X4_T(bf[0][0], bf[0][1], bf[1][0], bf[1][1],
                              vAddrBase + j0 * VSH_W * 4 + np * 32);
                    mma_f16(ao[2 * np], pa, bf[0][0], bf[0][1]);
                    mma_f16(ao[2 * np + 1], pa, bf[1][0], bf[1][1]);
                }
            }
        }

        sum1 += __shfl_xor_sync(0xffffffffu, sum1, 1);
        sum1 += __shfl_xor_sync(0xffffffffu, sum1, 2);
        sum2 += __shfl_xor_sync(0xffffffffu, sum2, 1);
        sum2 += __shfl_xor_sync(0xffffffffu, sum2, 2);
        float inv1 = 1.f / sum1;
        float inv2 = 1.f / sum2;

#pragma unroll
        for (int nt = 0; nt < 8; nt++) {
            int c = nt * 8 + lr * 2;
            if (r1 < SEQ)
                *(uint32_t*)&og[(size_t)(b * SEQ + r1) * DIM + h * HEAD_DIM + c] =
                    packh2(ao[nt][0] * inv1, ao[nt][1] * inv1);
            if (r2 < SEQ)
                *(uint32_t*)&og[(size_t)(b * SEQ + r2) * DIM + h * HEAD_DIM + c] =
                    packh2(ao[nt][2] * inv2, ao[nt][3] * inv2);
        }
    }
}

// ---------------- launch ----------------
extern "C" void kernel_launch(void* const* d_in, const int* in_sizes, int n_in,
                              void* d_out, int out_size)
{
    const float* x      = (const float*)d_in[0];
    const float* qk_w   = (const float*)d_in[1];
    const float* v_w    = (const float*)d_in[2];
    const float* w1_w   = (const float*)d_in[3];
    const float* w1_b   = (const float*)d_in[4];
    const float* w2     = (const float*)d_in[5];
    const float* b2     = (const float*)d_in[6];
    const float* proj_w = (const float*)d_in[7];
    const float* proj_b = (const float*)d_in[8];
    float* out = (float*)d_out;

    __half *xh, *qkvh, *oh, *qkvwh, *pwh;
    float* pos_buf;
    cudaGetSymbolAddress((void**)&xh, gx_h);
    cudaGetSymbolAddress((void**)&qkvh, gqkv_h);
    cudaGetSymbolAddress((void**)&oh, go_h);
    cudaGetSymbolAddress((void**)&qkvwh, gqkvw_h);
    cudaGetSymbolAddress((void**)&pwh, gpw_h);
    cudaGetSymbolAddress((void**)&pos_buf, g_pos);

    cudaFuncSetAttribute(gemm_h<false>, cudaFuncAttributeMaxDynamicSharedMemorySize, HSM_BYTES);
    cudaFuncSetAttribute(gemm_h<true>, cudaFuncAttributeMaxDynamicSharedMemorySize, HSM_BYTES);

    // merged converts
    conv_all<<<(NCONV_TOT / 4 + 255) / 256, 256>>>(x, qk_w, v_w, proj_w, xh, qkvwh, pwh);
    pos_kernel<<<729, 384>>>(w1_w, w1_b, w2, b2, pos_buf);

    // fused qkv projection: (12544, 2304)
    {
        dim3 grid(QKVS / 128, MTOT / 128);
        gemm_h<false><<<grid, 256, HSM_BYTES>>>(xh, qkvwh, nullptr, qkvh, MTOT, QKVS, DIM);
    }
    // fused attention
    {
        int smem_bytes = ATTN_SM_WORDS * 4;
        cudaFuncSetAttribute(attn_mma, cudaFuncAttributeMaxDynamicSharedMemorySize, smem_bytes);
        attn_mma<<<BATCH * HEADS, 256, smem_bytes>>>(qkvh, pos_buf, oh);
    }
    // output projection (float out, with bias)
    {
        dim3 grid(DIM / 128, MTOT / 128);
        gemm_h<true><<<grid, 256, HSM_BYTES>>>(oh, pwh, proj_b, out, MTOT, DIM, DIM);
    }
}